// round 11
// baseline (speedup 1.0000x reference)
#include <cuda_runtime.h>
#include <cuda_bf16.h>
#include <math.h>
#include <stdint.h>

#define NN 8192
#define HH 128
#define RR 8
#define BB 64
#define LL 48
#define EE 65536
#define VAC 64
#define NSEG (NN * RR)

// ---------------- scratch (device globals; no allocation) ----------------
__device__ float g_x[NN * HH];
__device__ __nv_bfloat16 g_xhi[NN * HH];
__device__ __nv_bfloat16 g_xlo[NN * HH];
__device__ __nv_bfloat16 g_wthi[27 * HH * HH];
__device__ __nv_bfloat16 g_wtlo[27 * HH * HH];
__device__ float g_y[NN * HH];
__device__ float g_z[NN * RR * HH];
__device__ int g_cnt[NSEG];                 // zeroed at static init; re-zeroed by gather#1
__device__ int g_cur[NSEG];
__device__ int g_off[NSEG];
__device__ int g_bt[64];
__device__ int g_bt2[64];
__device__ int g_esrc[EE];
__device__ float g_hG[BB * HH];
__device__ float g_seqin[BB * LL * HH];
__device__ float g_xw[BB * LL * 3 * HH];
__device__ float g_seqout[BB * LL * HH];
__device__ float g_A[BB * LL * HH];
__device__ float g_C[NN * HH];

__device__ __forceinline__ uint32_t smem_u32(const void* p) {
    uint32_t a;
    asm("{ .reg .u64 t; cvta.to.shared.u64 t, %1; cvt.u32.u64 %0, t; }" : "=r"(a) : "l"(p));
    return a;
}

// ---------------- embed + bf16 split + edge count (fused) ------------------
__global__ void k_embed_split(const int* __restrict__ nt, const float* __restrict__ emb,
                              const int* __restrict__ ei, const int* __restrict__ ea) {
    int i = blockIdx.x * blockDim.x + threadIdx.x;
    if (i < EE) atomicAdd(&g_cnt[ei[EE + i] * RR + ea[i]], 1);
    float v = emb[nt[i >> 7] * HH + (i & 127)];
    g_x[i] = v;
    __nv_bfloat16 hi = __float2bfloat16(v);
    g_xhi[i] = hi;
    g_xlo[i] = __float2bfloat16(v - __bfloat162float(hi));
}

// ---------------- CSR build: 2-level scan + scatter ----------------
__global__ void __launch_bounds__(1024) k_scan1() {
    __shared__ int s[1024];
    int i = blockIdx.x * 1024 + threadIdx.x;
    int v = g_cnt[i];
    s[threadIdx.x] = v;
    __syncthreads();
#pragma unroll
    for (int off = 1; off < 1024; off <<= 1) {
        int t = (threadIdx.x >= off) ? s[threadIdx.x - off] : 0;
        __syncthreads();
        s[threadIdx.x] += t;
        __syncthreads();
    }
    g_off[i] = s[threadIdx.x] - v;
    if (threadIdx.x == 1023) g_bt[blockIdx.x] = s[1023];
}
__global__ void k_scan2() {
    __shared__ int s[64];
    int v = g_bt[threadIdx.x];
    s[threadIdx.x] = v;
    __syncthreads();
#pragma unroll
    for (int off = 1; off < 64; off <<= 1) {
        int t = (threadIdx.x >= off) ? s[threadIdx.x - off] : 0;
        __syncthreads();
        s[threadIdx.x] += t;
        __syncthreads();
    }
    g_bt2[threadIdx.x] = s[threadIdx.x] - v;
}
__global__ void k_scatter(const int* __restrict__ ei, const int* __restrict__ ea) {
    int e = blockIdx.x * blockDim.x + threadIdx.x;
    if (e >= EE) return;
    int seg = ei[EE + e] * RR + ea[e];
    int pos = g_off[seg] + g_bt2[seg >> 10] + atomicAdd(&g_cur[seg], 1);
    g_esrc[pos] = ei[e];
}

// ---------------- weight transpose + split (smem-tiled) --------------------
__global__ void k_convw(const float* __restrict__ rel, const float* __restrict__ root) {
    __shared__ float ts[32][33];
    int w = blockIdx.y;
    int li = w / 9, cb = w % 9;
    const float* W = (cb < 8) ? rel + (size_t)(li * 8 + cb) * (HH * HH)
                              : root + (size_t)li * (HH * HH);
    int tx = (blockIdx.x & 3) * 32;
    int ty = (blockIdx.x >> 2) * 32;
    int r = threadIdx.x >> 5;
    int c = threadIdx.x & 31;
#pragma unroll
    for (int i = 0; i < 32; i += 8)
        ts[r + i][c] = W[(size_t)(ty + r + i) * HH + tx + c];
    __syncthreads();
    size_t base = (size_t)w * HH * HH;
#pragma unroll
    for (int i = 0; i < 32; i += 8) {
        float v = ts[c][r + i];
        __nv_bfloat16 hi = __float2bfloat16(v);
        size_t p = base + (size_t)(tx + r + i) * HH + ty + c;
        g_wthi[p] = hi;
        g_wtlo[p] = __float2bfloat16(v - __bfloat162float(hi));
    }
}

// ====== RGCN GEMM: mma.sync bf16, 128-row tiles, 512 thr, 4Mx4N ============
#define LDT 136
#define TILE_B (128 * LDT * 2)
#define RGCN_SMEM (4 * TILE_B)

#define MMA16816(d, a0, a1, a2, a3, b0, b1)                                 \
    asm volatile("mma.sync.aligned.m16n8k16.row.col.f32.bf16.bf16.f32 "     \
                 "{%0,%1,%2,%3}, {%4,%5,%6,%7}, {%8,%9}, {%0,%1,%2,%3};"    \
                 : "+f"((d)[0]), "+f"((d)[1]), "+f"((d)[2]), "+f"((d)[3])   \
                 : "r"(a0), "r"(a1), "r"(a2), "r"(a3), "r"(b0), "r"(b1))

#define LDMX4(r0, r1, r2, r3, addr)                                         \
    asm volatile("ldmatrix.sync.aligned.m8n8.x4.shared.b16 {%0,%1,%2,%3}, [%4];" \
                 : "=r"(r0), "=r"(r1), "=r"(r2), "=r"(r3) : "r"(addr))

__global__ void __launch_bounds__(512) k_rgcn_mma(const float* __restrict__ bias, int li) {
    extern __shared__ char sm[];
    __shared__ float s_bias[HH];

    int tid = threadIdx.x;
    int cb = blockIdx.x, mb = blockIdx.y;
    int m0 = mb * 128;
    int widx = li * 9 + cb;

    if (cb == 8 && tid < HH) s_bias[tid] = bias[li * HH + tid];

    {
        const uint4* srcs[4] = {
            (const uint4*)(g_xhi + (size_t)m0 * HH),
            (const uint4*)(g_xlo + (size_t)m0 * HH),
            (const uint4*)(g_wthi + (size_t)widx * HH * HH),
            (const uint4*)(g_wtlo + (size_t)widx * HH * HH)};
#pragma unroll
        for (int ti = 0; ti < 4; ti++) {
            const uint4* src = srcs[ti];
            char* dst = sm + ti * TILE_B;
#pragma unroll
            for (int t = 0; t < 4; t++) {
                int c = tid + t * 512;
                int r = c >> 4, q = c & 15;
                *(uint4*)(dst + r * (LDT * 2) + q * 16) = src[r * 16 + q];
            }
        }
    }
    __syncthreads();

    int lane = tid & 31, wid = tid >> 5;
    int warpM = wid & 3;
    int warpN = wid >> 2;
    int g = lane >> 2, tg = lane & 3;

    uint32_t smbase = smem_u32(sm);
    uint32_t aOff = (uint32_t)((warpM * 32 + (lane & 15)) * LDT + ((lane & 16) ? 8 : 0)) * 2;
    uint32_t bOff = (uint32_t)((warpN * 32 + (lane & 7) + ((lane & 16) ? 8 : 0)) * LDT +
                               ((lane & 8) ? 8 : 0)) * 2;

    uint32_t aH = smbase + aOff;
    uint32_t aL = smbase + TILE_B + aOff;
    uint32_t bH = smbase + 2 * TILE_B + bOff;
    uint32_t bL = smbase + 3 * TILE_B + bOff;

    float acc[2][4][4];
#pragma unroll
    for (int mi = 0; mi < 2; mi++)
#pragma unroll
        for (int nf = 0; nf < 4; nf++)
#pragma unroll
            for (int j = 0; j < 4; j++) acc[mi][nf][j] = 0.f;

#pragma unroll
    for (int kc = 0; kc < 8; kc++) {
        uint32_t kb = kc * 32;
        uint32_t ah[2][4], al[2][4];
        LDMX4(ah[0][0], ah[0][1], ah[0][2], ah[0][3], aH + kb);
        LDMX4(ah[1][0], ah[1][1], ah[1][2], ah[1][3], aH + 16 * LDT * 2 + kb);
        LDMX4(al[0][0], al[0][1], al[0][2], al[0][3], aL + kb);
        LDMX4(al[1][0], al[1][1], al[1][2], al[1][3], aL + 16 * LDT * 2 + kb);
#pragma unroll
        for (int p = 0; p < 2; p++) {
            uint32_t bh0, bh1, bh2, bh3, bl0, bl1, bl2, bl3;
            LDMX4(bh0, bh1, bh2, bh3, bH + p * (16 * LDT * 2) + kb);
            LDMX4(bl0, bl1, bl2, bl3, bL + p * (16 * LDT * 2) + kb);
#pragma unroll
            for (int mi = 0; mi < 2; mi++) {
                MMA16816(acc[mi][2 * p],     ah[mi][0], ah[mi][1], ah[mi][2], ah[mi][3], bh0, bh1);
                MMA16816(acc[mi][2 * p + 1], ah[mi][0], ah[mi][1], ah[mi][2], ah[mi][3], bh2, bh3);
                MMA16816(acc[mi][2 * p],     ah[mi][0], ah[mi][1], ah[mi][2], ah[mi][3], bl0, bl1);
                MMA16816(acc[mi][2 * p + 1], ah[mi][0], ah[mi][1], ah[mi][2], ah[mi][3], bl2, bl3);
                MMA16816(acc[mi][2 * p],     al[mi][0], al[mi][1], al[mi][2], al[mi][3], bh0, bh1);
                MMA16816(acc[mi][2 * p + 1], al[mi][0], al[mi][1], al[mi][2], al[mi][3], bh2, bh3);
            }
        }
    }

#pragma unroll
    for (int mi = 0; mi < 2; mi++) {
        int r0 = m0 + warpM * 32 + mi * 16 + g;
#pragma unroll
        for (int nf = 0; nf < 4; nf++) {
            int col = warpN * 32 + nf * 8 + tg * 2;
            if (cb < 8) {
                float2* z0 = (float2*)(g_z + (size_t)r0 * (RR * HH) + cb * HH + col);
                float2* z1 = (float2*)(g_z + (size_t)(r0 + 8) * (RR * HH) + cb * HH + col);
                *z0 = make_float2(acc[mi][nf][0], acc[mi][nf][1]);
                *z1 = make_float2(acc[mi][nf][2], acc[mi][nf][3]);
            } else {
                float b0 = s_bias[col], b1 = s_bias[col + 1];
                float2* y0 = (float2*)(g_y + (size_t)r0 * HH + col);
                float2* y1 = (float2*)(g_y + (size_t)(r0 + 8) * HH + col);
                *y0 = make_float2(acc[mi][nf][0] + b0, acc[mi][nf][1] + b1);
                *y1 = make_float2(acc[mi][nf][2] + b0, acc[mi][nf][3] + b1);
            }
        }
    }
}

// ------------- gather + relu + bf16 split (R7) + optional counter re-zero --
__device__ __forceinline__ int segoff(int s) { return g_off[s] + g_bt2[s >> 10]; }

__global__ void __launch_bounds__(256) k_gather_relu(int zero_cnt) {
    int gtid = blockIdx.x * blockDim.x + threadIdx.x;
    if (zero_cnt && gtid < NSEG) { g_cnt[gtid] = 0; g_cur[gtid] = 0; }
    int node = gtid >> 5;
    int lane = threadIdx.x & 31;
    if (node >= NN) return;

    float4 acc = ((const float4*)(g_y + (size_t)node * HH))[lane];
    int st = segoff(node * RR);
#pragma unroll
    for (int r = 0; r < RR; r++) {
        int sn = node * RR + r + 1;
        int en = (sn < NSEG) ? segoff(sn) : EE;
        int cnt = en - st;
        if (cnt > 0) {
            float4 a = make_float4(0.f, 0.f, 0.f, 0.f);
            for (int j = st; j < en; j++) {
                int src = g_esrc[j];
                float4 z = *(const float4*)&g_z[(size_t)src * (RR * HH) + r * HH + lane * 4];
                a.x += z.x; a.y += z.y; a.z += z.z; a.w += z.w;
            }
            float sc = 1.0f / (float)cnt;
            acc.x += a.x * sc; acc.y += a.y * sc;
            acc.z += a.z * sc; acc.w += a.w * sc;
        }
        st = en;
    }
    acc.x = fmaxf(acc.x, 0.f); acc.y = fmaxf(acc.y, 0.f);
    acc.z = fmaxf(acc.z, 0.f); acc.w = fmaxf(acc.w, 0.f);

    ((float4*)(g_x + (size_t)node * HH))[lane] = acc;

    __nv_bfloat162 h0 = make_bfloat162(__float2bfloat16(acc.x), __float2bfloat16(acc.y));
    __nv_bfloat162 h1 = make_bfloat162(__float2bfloat16(acc.z), __float2bfloat16(acc.w));
    __nv_bfloat162 l0 = make_bfloat162(
        __float2bfloat16(acc.x - __bfloat162float(h0.x)),
        __float2bfloat16(acc.y - __bfloat162float(h0.y)));
    __nv_bfloat162 l1 = make_bfloat162(
        __float2bfloat16(acc.z - __bfloat162float(h1.x)),
        __float2bfloat16(acc.w - __bfloat162float(h1.y)));
    ((__nv_bfloat162*)(g_xhi + (size_t)node * HH))[lane * 2] = h0;
    ((__nv_bfloat162*)(g_xhi + (size_t)node * HH))[lane * 2 + 1] = h1;
    ((__nv_bfloat162*)(g_xlo + (size_t)node * HH))[lane * 2] = l0;
    ((__nv_bfloat162*)(g_xlo + (size_t)node * HH))[lane * 2 + 1] = l1;
}

// --------- pool + action head + sos + seqemb (fused, grid (LL, BB)) --------
__global__ void k_pool_seqemb(const int* __restrict__ nodes_bs,
                              const float* __restrict__ wA, const float* __restrict__ bA,
                              const float* __restrict__ wAf, const float* __restrict__ bAf,
                              const int* __restrict__ act, const float* __restrict__ embA,
                              const float* __restrict__ seq, float* __restrict__ out) {
    int b = blockIdx.y;
    if (blockIdx.x == 0) {
        // pool + action + sos for graph b
        int o = threadIdx.x;
        __shared__ float sg[HH], t1[HH];
        float s = 0.f;
        const float* xp = g_x + (size_t)b * (NN / BB) * HH + o;
#pragma unroll 4
        for (int j = 0; j < NN / BB; j++) s += xp[j * HH];
        s /= (float)nodes_bs[b];
        g_hG[b * HH + o] = s;
        sg[o] = s;
        g_seqin[(size_t)b * LL * HH + o] = embA[act[b] * HH + o];
        __syncthreads();
        float acc = bA[o];
        const float* w = wA + o * HH;
#pragma unroll 8
        for (int h = 0; h < HH; h += 4) {
            float4 w4 = *(const float4*)&w[h];
            acc += sg[h] * w4.x + sg[h + 1] * w4.y + sg[h + 2] * w4.z + sg[h + 3] * w4.w;
        }
        t1[o] = fmaxf(acc, 0.f);
        __syncthreads();
        if (o < VAC) {
            float a2 = bAf[o];
            const float* w2 = wAf + o * HH;
#pragma unroll 8
            for (int h = 0; h < HH; h += 4) {
                float4 w4 = *(const float4*)&w2[h];
                a2 += t1[h] * w4.x + t1[h + 1] * w4.y + t1[h + 2] * w4.z + t1[h + 3] * w4.w;
            }
            out[b * VAC + o] = a2;
        }
    } else {
        int t = blockIdx.x - 1;          // 0..LL-2
        int h = threadIdx.x;
        __shared__ float s[NN / BB];
        s[h] = seq[(size_t)(b * (NN / BB) + h) * LL + t];
        __syncthreads();
        float acc = 0.f;
        for (int j = 0; j < NN / BB; j++) {
            float sv = s[j];
            if (sv != 0.0f)
                acc += sv * g_x[(size_t)(b * (NN / BB) + j) * HH + h];
        }
        g_seqin[((size_t)b * LL + t + 1) * HH + h] = acc;
    }
}

// --------- fused GRU-xw + node-C GEMM (blocks [0,192)=xw, [192,704)=C) -----
__global__ void __launch_bounds__(384) k_gemmT_xwC(
    const float* __restrict__ w_ih, const float* __restrict__ b_ih,
    const float* __restrict__ w_n, const float* __restrict__ b_n) {
    int bx = blockIdx.x;
    int tid = threadIdx.x;
    __shared__ float Xs[16 * HH];
    if (bx < (BB * LL) / 16) {
        int m0 = bx * 16;
        for (int idx = tid; idx < 16 * HH; idx += 384) Xs[idx] = g_seqin[(size_t)m0 * HH + idx];
        __syncthreads();
        int j = tid;   // 0..383
        float acc[16];
        float bv = b_ih[j];
#pragma unroll
        for (int m = 0; m < 16; m++) acc[m] = bv;
        const float* wr = w_ih + (size_t)j * HH;
        for (int h = 0; h < HH; h += 4) {
            float4 w4 = *(const float4*)&wr[h];
#pragma unroll
            for (int m = 0; m < 16; m++) {
                acc[m] += Xs[m * HH + h] * w4.x;
                acc[m] += Xs[m * HH + h + 1] * w4.y;
                acc[m] += Xs[m * HH + h + 2] * w4.z;
                acc[m] += Xs[m * HH + h + 3] * w4.w;
            }
        }
#pragma unroll
        for (int m = 0; m < 16; m++) g_xw[(size_t)(m0 + m) * (3 * HH) + j] = acc[m];
    } else {
        int m0 = (bx - (BB * LL) / 16) * 16;
        for (int idx = tid; idx < 16 * HH; idx += 384) Xs[idx] = g_x[(size_t)m0 * HH + idx];
        __syncthreads();
        if (tid >= HH) return;
        int j = tid;
        float acc[16];
        float bv = b_n[j];
#pragma unroll
        for (int m = 0; m < 16; m++) acc[m] = bv;
        const float* wr = w_n + (size_t)j * (2 * HH) + HH;
        for (int h = 0; h < HH; h += 4) {
            float4 w4 = *(const float4*)&wr[h];
#pragma unroll
            for (int m = 0; m < 16; m++) {
                acc[m] += Xs[m * HH + h] * w4.x;
                acc[m] += Xs[m * HH + h + 1] * w4.y;
                acc[m] += Xs[m * HH + h + 2] * w4.z;
                acc[m] += Xs[m * HH + h + 3] * w4.w;
            }
        }
#pragma unroll
        for (int m = 0; m < 16; m++) g_C[(size_t)(m0 + m) * HH + j] = acc[m];
    }
}

// ---------------- A = seqout @ W1^T (192 blocks, 128 thr) ------------------
__global__ void k_gemmT_A(const float* __restrict__ w_n) {
    int m0 = blockIdx.x * 16;
    int j = threadIdx.x;
    __shared__ float Xs[16 * HH];
    for (int idx = j; idx < 16 * HH; idx += HH) Xs[idx] = g_seqout[(size_t)m0 * HH + idx];
    __syncthreads();
    float acc[16];
#pragma unroll
    for (int m = 0; m < 16; m++) acc[m] = 0.f;
    const float* wr = w_n + (size_t)j * (2 * HH);
    for (int h = 0; h < HH; h += 4) {
        float4 w4 = *(const float4*)&wr[h];
#pragma unroll
        for (int m = 0; m < 16; m++) {
            acc[m] += Xs[m * HH + h] * w4.x;
            acc[m] += Xs[m * HH + h + 1] * w4.y;
            acc[m] += Xs[m * HH + h + 2] * w4.z;
            acc[m] += Xs[m * HH + h + 3] * w4.w;
        }
    }
#pragma unroll
    for (int m = 0; m < 16; m++) g_A[(size_t)(m0 + m) * HH + j] = acc[m];
}

// ---------------- GRU scan (float4 smem reads, R7 version) ----------------
__global__ void __launch_bounds__(384) k_gru(const float* __restrict__ w_hh,
                                             const float* __restrict__ b_hh,
                                             const int* __restrict__ len_seq) {
    int b = blockIdx.x;
    int g = threadIdx.x;
    __shared__ __align__(16) float sh[HH];
    __shared__ float sg[3 * HH];
    if (g < HH) sh[g] = g_hG[b * HH + g];
    int ls = len_seq[b];
    const float* w = w_hh + (size_t)g * HH;
    float bg = b_hh[g];
    __syncthreads();
    const float4* sh4 = (const float4*)sh;
    for (int t = 0; t < LL; t++) {
        float acc = bg;
#pragma unroll
        for (int k = 0; k < HH / 4; k++) {
            float4 w4 = *(const float4*)&w[k * 4];
            float4 h4 = sh4[k];
            acc += h4.x * w4.x + h4.y * w4.y + h4.z * w4.z + h4.w * w4.w;
        }
        sg[g] = acc;
        __syncthreads();
        if (g < HH) {
            const float* xwp = g_xw + ((size_t)b * LL + t) * (3 * HH);
            float rg = 1.f / (1.f + expf(-(xwp[g] + sg[g])));
            float zg = 1.f / (1.f + expf(-(xwp[HH + g] + sg[HH + g])));
            float ng = tanhf(xwp[2 * HH + g] + rg * sg[2 * HH + g]);
            float hnew = (1.f - zg) * ng + zg * sh[g];
            g_seqout[((size_t)b * LL + t) * HH + g] = (t < ls) ? hnew : 0.f;
            sh[g] = hnew;
        }
        __syncthreads();
    }
}

// ------- fused node logits + per-graph softmax (block per graph) -----------
#define NPG (NN / BB)    // 128
#define LSM_SMEM ((LL * HH + LL * 129 + 2 * LL) * 4)
__global__ void __launch_bounds__(256) k_logits_softmax(
    const int* __restrict__ bs, const float* __restrict__ wf,
    const float* __restrict__ bf, float* __restrict__ outN) {
    extern __shared__ float dyn[];
    float* As = dyn;                     // LL*HH
    float* lg = As + LL * HH;            // LL*129
    float* smax = lg + LL * 129;         // LL
    float* ssum = smax + LL;             // LL
    int b = blockIdx.x;
    int tid = threadIdx.x;
    int w = tid >> 5, lane = tid & 31;

    // stage A[b] (48 x 128)
    for (int idx = tid; idx < LL * HH; idx += 256)
        As[idx] = g_A[(size_t)b * LL * HH + idx];
    __syncthreads();

    float4 w4 = *(const float4*)&wf[lane * 4];
    float bias = bf[0];

    // logits: warp w handles nodes w, w+8, ...
    for (int node = w; node < NPG; node += 8) {
        int gi = b * NPG + node;
        float4 c4 = *(const float4*)&g_C[(size_t)gi * HH + lane * 4];
        for (int t0 = 0; t0 < LL; t0 += 4) {
            float s[4];
#pragma unroll
            for (int q = 0; q < 4; q++) {
                float4 a4 = *(const float4*)&As[(t0 + q) * HH + lane * 4];
                s[q] = fmaxf(a4.x + c4.x, 0.f) * w4.x
                     + fmaxf(a4.y + c4.y, 0.f) * w4.y
                     + fmaxf(a4.z + c4.z, 0.f) * w4.z
                     + fmaxf(a4.w + c4.w, 0.f) * w4.w;
            }
#pragma unroll
            for (int off = 16; off; off >>= 1) {
#pragma unroll
                for (int q = 0; q < 4; q++)
                    s[q] += __shfl_down_sync(0xffffffffu, s[q], off);
            }
            if (lane == 0) {
#pragma unroll
                for (int q = 0; q < 4; q++)
                    lg[(t0 + q) * 129 + node] = s[q] + bias;
            }
        }
    }
    __syncthreads();

    // per-t softmax over 128 nodes
    for (int t = w; t < LL; t += 8) {
        float v0 = lg[t * 129 + lane];
        float v1 = lg[t * 129 + lane + 32];
        float v2 = lg[t * 129 + lane + 64];
        float v3 = lg[t * 129 + lane + 96];
        float mx = fmaxf(fmaxf(v0, v1), fmaxf(v2, v3));
#pragma unroll
        for (int off = 16; off; off >>= 1)
            mx = fmaxf(mx, __shfl_xor_sync(0xffffffffu, mx, off));
        float e = expf(v0 - mx) + expf(v1 - mx) + expf(v2 - mx) + expf(v3 - mx);
#pragma unroll
        for (int off = 16; off; off >>= 1) e += __shfl_xor_sync(0xffffffffu, e, off);
        if (lane == 0) { smax[t] = mx; ssum[t] = e; }
    }
    __syncthreads();

    float* base = outN + (size_t)b * NPG * LL;
    for (int idx = tid; idx < NPG * LL; idx += 256) {
        int node = idx / LL, t = idx % LL;
        base[idx] = expf(lg[t * 129 + node] - smax[t]) / ssum[t];
    }
}

// ---------------- launch ----------------
extern "C" void kernel_launch(void* const* d_in, const int* in_sizes, int n_in,
                              void* d_out, int out_size) {
    const int* nodeTypes   = (const int*)d_in[0];
    const int* edge_index  = (const int*)d_in[1];
    const int* edge_attr   = (const int*)d_in[2];
    const int* bs          = (const int*)d_in[3];
    const int* nodes_bs    = (const int*)d_in[4];
    const int* len_seq     = (const int*)d_in[5];
    const float* seq       = (const float*)d_in[6];
    const int* action_in   = (const int*)d_in[7];
    const float* emb_nodes = (const float*)d_in[8];
    const float* emb_act   = (const float*)d_in[9];
    const float* rgcn_rel  = (const float*)d_in[10];
    const float* rgcn_root = (const float*)d_in[11];
    const float* rgcn_bias = (const float*)d_in[12];
    const float* gru_w_ih  = (const float*)d_in[13];
    const float* gru_w_hh  = (const float*)d_in[14];
    const float* gru_b_ih  = (const float*)d_in[15];
    const float* gru_b_hh  = (const float*)d_in[16];
    const float* linA_w    = (const float*)d_in[17];
    const float* linA_b    = (const float*)d_in[18];
    const float* linAf_w   = (const float*)d_in[19];
    const float* linAf_b   = (const float*)d_in[20];
    const float* linN_w    = (const float*)d_in[21];
    const float* linN_b    = (const float*)d_in[22];
    const float* linNf_w   = (const float*)d_in[23];
    const float* linNf_b   = (const float*)d_in[24];

    float* out_action = (float*)d_out;
    float* out_nodes  = out_action + BB * VAC;

    cudaFuncSetAttribute(k_rgcn_mma, cudaFuncAttributeMaxDynamicSharedMemorySize, RGCN_SMEM);
    cudaFuncSetAttribute(k_logits_softmax, cudaFuncAttributeMaxDynamicSharedMemorySize, LSM_SMEM);

    // 1: embed + count   2: convw   3: scan1   4: MMA li=0 (profiled)
    k_embed_split<<<(NN * HH) / 256, 256>>>(nodeTypes, emb_nodes, edge_index, edge_attr);
    k_convw<<<dim3(16, 27), 256>>>(rgcn_rel, rgcn_root);
    k_scan1<<<64, 1024>>>();
    k_rgcn_mma<<<dim3(9, 64), 512, RGCN_SMEM>>>(rgcn_bias, 0);

    k_scan2<<<1, 64>>>();
    k_scatter<<<EE / 256, 256>>>(edge_index, edge_attr);

    k_gather_relu<<<NN / 8, 256>>>(1);     // also re-zeroes g_cnt/g_cur for next replay
    for (int li = 1; li < 3; li++) {
        k_rgcn_mma<<<dim3(9, 64), 512, RGCN_SMEM>>>(rgcn_bias, li);
        k_gather_relu<<<NN / 8, 256>>>(0);
    }

    k_pool_seqemb<<<dim3(LL, BB), HH>>>(nodes_bs, linA_w, linA_b, linAf_w, linAf_b,
                                        action_in, emb_act, seq, out_action);

    k_gemmT_xwC<<<(BB * LL) / 16 + NN / 16, 384>>>(gru_w_ih, gru_b_ih, linN_w, linN_b);
    k_gru<<<BB, 3 * HH>>>(gru_w_hh, gru_b_hh, len_seq);
    k_gemmT_A<<<(BB * LL) / 16, HH>>>(linN_w);

    k_logits_softmax<<<BB, 256, LSM_SMEM>>>(bs, linNf_w, linNf_b, out_nodes);
}

// round 12
// speedup vs baseline: 1.0431x; 1.0431x over previous
#include <cuda_runtime.h>
#include <cuda_bf16.h>
#include <math.h>
#include <stdint.h>

#define NN 8192
#define HH 128
#define RR 8
#define BB 64
#define LL 48
#define EE 65536
#define VAC 64
#define NSEG (NN * RR)
#define NPG (NN / BB)

// ---------------- scratch (device globals; no allocation) ----------------
__device__ float g_x[NN * HH];
__device__ __nv_bfloat16 g_xhi[NN * HH];
__device__ __nv_bfloat16 g_xlo[NN * HH];
__device__ __nv_bfloat16 g_wthi[27 * HH * HH];
__device__ __nv_bfloat16 g_wtlo[27 * HH * HH];
__device__ float g_y[NN * HH];
__device__ float g_z[NN * RR * HH];
__device__ int g_cnt[NSEG];                // zero at init; re-zeroed by gather#1
__device__ int g_cur[NSEG];
__device__ int g_off[NSEG];
__device__ int g_bt[64];
__device__ int g_bt2[64];
__device__ int g_esrc[EE];
__device__ float g_hG[BB * HH];
__device__ float g_seqT[BB * LL * NPG];    // transposed sequence input
__device__ float g_seqin[BB * LL * HH];
__device__ float g_xw[BB * LL * 3 * HH];
__device__ float g_seqout[BB * LL * HH];
__device__ float g_A[BB * LL * HH];
__device__ float g_C[NN * HH];

__device__ __forceinline__ uint32_t smem_u32(const void* p) {
    uint32_t a;
    asm("{ .reg .u64 t; cvta.to.shared.u64 t, %1; cvt.u32.u64 %0, t; }" : "=r"(a) : "l"(p));
    return a;
}

// ---------------- embed + bf16 split + edge count (fused) ------------------
__global__ void k_embed_split(const int* __restrict__ nt, const float* __restrict__ emb,
                              const int* __restrict__ ei, const int* __restrict__ ea) {
    int i = blockIdx.x * blockDim.x + threadIdx.x;
    if (i < EE) atomicAdd(&g_cnt[ei[EE + i] * RR + ea[i]], 1);
    float v = emb[nt[i >> 7] * HH + (i & 127)];
    g_x[i] = v;
    __nv_bfloat16 hi = __float2bfloat16(v);
    g_xhi[i] = hi;
    g_xlo[i] = __float2bfloat16(v - __bfloat162float(hi));
}

// ---------------- CSR build: 2-level scan + scatter ----------------
__global__ void __launch_bounds__(1024) k_scan1() {
    __shared__ int s[1024];
    int i = blockIdx.x * 1024 + threadIdx.x;
    int v = g_cnt[i];
    s[threadIdx.x] = v;
    __syncthreads();
#pragma unroll
    for (int off = 1; off < 1024; off <<= 1) {
        int t = (threadIdx.x >= off) ? s[threadIdx.x - off] : 0;
        __syncthreads();
        s[threadIdx.x] += t;
        __syncthreads();
    }
    g_off[i] = s[threadIdx.x] - v;
    if (threadIdx.x == 1023) g_bt[blockIdx.x] = s[1023];
}
__global__ void k_scan2() {
    __shared__ int s[64];
    int v = g_bt[threadIdx.x];
    s[threadIdx.x] = v;
    __syncthreads();
#pragma unroll
    for (int off = 1; off < 64; off <<= 1) {
        int t = (threadIdx.x >= off) ? s[threadIdx.x - off] : 0;
        __syncthreads();
        s[threadIdx.x] += t;
        __syncthreads();
    }
    g_bt2[threadIdx.x] = s[threadIdx.x] - v;
}
__global__ void k_scatter(const int* __restrict__ ei, const int* __restrict__ ea) {
    int e = blockIdx.x * blockDim.x + threadIdx.x;
    if (e >= EE) return;
    int seg = ei[EE + e] * RR + ea[e];
    int pos = g_off[seg] + g_bt2[seg >> 10] + atomicAdd(&g_cur[seg], 1);
    g_esrc[pos] = ei[e];
}

// ---------------- weight transpose + split (smem-tiled) --------------------
__global__ void k_convw(const float* __restrict__ rel, const float* __restrict__ root) {
    __shared__ float ts[32][33];
    int w = blockIdx.y;
    int li = w / 9, cb = w % 9;
    const float* W = (cb < 8) ? rel + (size_t)(li * 8 + cb) * (HH * HH)
                              : root + (size_t)li * (HH * HH);
    int tx = (blockIdx.x & 3) * 32;
    int ty = (blockIdx.x >> 2) * 32;
    int r = threadIdx.x >> 5;
    int c = threadIdx.x & 31;
#pragma unroll
    for (int i = 0; i < 32; i += 8)
        ts[r + i][c] = W[(size_t)(ty + r + i) * HH + tx + c];
    __syncthreads();
    size_t base = (size_t)w * HH * HH;
#pragma unroll
    for (int i = 0; i < 32; i += 8) {
        float v = ts[c][r + i];
        __nv_bfloat16 hi = __float2bfloat16(v);
        size_t p = base + (size_t)(tx + r + i) * HH + ty + c;
        g_wthi[p] = hi;
        g_wtlo[p] = __float2bfloat16(v - __bfloat162float(hi));
    }
}

// ====== RGCN GEMM: mma.sync bf16, 128-row tiles, 512 thr, 4Mx4N ============
#define LDT 136
#define TILE_B (128 * LDT * 2)
#define RGCN_SMEM (4 * TILE_B)

#define MMA16816(d, a0, a1, a2, a3, b0, b1)                                 \
    asm volatile("mma.sync.aligned.m16n8k16.row.col.f32.bf16.bf16.f32 "     \
                 "{%0,%1,%2,%3}, {%4,%5,%6,%7}, {%8,%9}, {%0,%1,%2,%3};"    \
                 : "+f"((d)[0]), "+f"((d)[1]), "+f"((d)[2]), "+f"((d)[3])   \
                 : "r"(a0), "r"(a1), "r"(a2), "r"(a3), "r"(b0), "r"(b1))

#define LDMX4(r0, r1, r2, r3, addr)                                         \
    asm volatile("ldmatrix.sync.aligned.m8n8.x4.shared.b16 {%0,%1,%2,%3}, [%4];" \
                 : "=r"(r0), "=r"(r1), "=r"(r2), "=r"(r3) : "r"(addr))

__global__ void __launch_bounds__(512) k_rgcn_mma(const float* __restrict__ bias, int li) {
    extern __shared__ char sm[];
    __shared__ float s_bias[HH];

    int tid = threadIdx.x;
    int cb = blockIdx.x, mb = blockIdx.y;
    int m0 = mb * 128;
    int widx = li * 9 + cb;

    if (cb == 8 && tid < HH) s_bias[tid] = bias[li * HH + tid];

    {
        const uint4* srcs[4] = {
            (const uint4*)(g_xhi + (size_t)m0 * HH),
            (const uint4*)(g_xlo + (size_t)m0 * HH),
            (const uint4*)(g_wthi + (size_t)widx * HH * HH),
            (const uint4*)(g_wtlo + (size_t)widx * HH * HH)};
#pragma unroll
        for (int ti = 0; ti < 4; ti++) {
            const uint4* src = srcs[ti];
            char* dst = sm + ti * TILE_B;
#pragma unroll
            for (int t = 0; t < 4; t++) {
                int c = tid + t * 512;
                int r = c >> 4, q = c & 15;
                *(uint4*)(dst + r * (LDT * 2) + q * 16) = src[r * 16 + q];
            }
        }
    }
    __syncthreads();

    int lane = tid & 31, wid = tid >> 5;
    int warpM = wid & 3;
    int warpN = wid >> 2;
    int g = lane >> 2, tg = lane & 3;

    uint32_t smbase = smem_u32(sm);
    uint32_t aOff = (uint32_t)((warpM * 32 + (lane & 15)) * LDT + ((lane & 16) ? 8 : 0)) * 2;
    uint32_t bOff = (uint32_t)((warpN * 32 + (lane & 7) + ((lane & 16) ? 8 : 0)) * LDT +
                               ((lane & 8) ? 8 : 0)) * 2;

    uint32_t aH = smbase + aOff;
    uint32_t aL = smbase + TILE_B + aOff;
    uint32_t bH = smbase + 2 * TILE_B + bOff;
    uint32_t bL = smbase + 3 * TILE_B + bOff;

    float acc[2][4][4];
#pragma unroll
    for (int mi = 0; mi < 2; mi++)
#pragma unroll
        for (int nf = 0; nf < 4; nf++)
#pragma unroll
            for (int j = 0; j < 4; j++) acc[mi][nf][j] = 0.f;

#pragma unroll
    for (int kc = 0; kc < 8; kc++) {
        uint32_t kb = kc * 32;
        uint32_t ah[2][4], al[2][4];
        LDMX4(ah[0][0], ah[0][1], ah[0][2], ah[0][3], aH + kb);
        LDMX4(ah[1][0], ah[1][1], ah[1][2], ah[1][3], aH + 16 * LDT * 2 + kb);
        LDMX4(al[0][0], al[0][1], al[0][2], al[0][3], aL + kb);
        LDMX4(al[1][0], al[1][1], al[1][2], al[1][3], aL + 16 * LDT * 2 + kb);
#pragma unroll
        for (int p = 0; p < 2; p++) {
            uint32_t bh0, bh1, bh2, bh3, bl0, bl1, bl2, bl3;
            LDMX4(bh0, bh1, bh2, bh3, bH + p * (16 * LDT * 2) + kb);
            LDMX4(bl0, bl1, bl2, bl3, bL + p * (16 * LDT * 2) + kb);
#pragma unroll
            for (int mi = 0; mi < 2; mi++) {
                MMA16816(acc[mi][2 * p],     ah[mi][0], ah[mi][1], ah[mi][2], ah[mi][3], bh0, bh1);
                MMA16816(acc[mi][2 * p + 1], ah[mi][0], ah[mi][1], ah[mi][2], ah[mi][3], bh2, bh3);
                MMA16816(acc[mi][2 * p],     ah[mi][0], ah[mi][1], ah[mi][2], ah[mi][3], bl0, bl1);
                MMA16816(acc[mi][2 * p + 1], ah[mi][0], ah[mi][1], ah[mi][2], ah[mi][3], bl2, bl3);
                MMA16816(acc[mi][2 * p],     al[mi][0], al[mi][1], al[mi][2], al[mi][3], bh0, bh1);
                MMA16816(acc[mi][2 * p + 1], al[mi][0], al[mi][1], al[mi][2], al[mi][3], bh2, bh3);
            }
        }
    }

#pragma unroll
    for (int mi = 0; mi < 2; mi++) {
        int r0 = m0 + warpM * 32 + mi * 16 + g;
#pragma unroll
        for (int nf = 0; nf < 4; nf++) {
            int col = warpN * 32 + nf * 8 + tg * 2;
            if (cb < 8) {
                float2* z0 = (float2*)(g_z + (size_t)r0 * (RR * HH) + cb * HH + col);
                float2* z1 = (float2*)(g_z + (size_t)(r0 + 8) * (RR * HH) + cb * HH + col);
                *z0 = make_float2(acc[mi][nf][0], acc[mi][nf][1]);
                *z1 = make_float2(acc[mi][nf][2], acc[mi][nf][3]);
            } else {
                float b0 = s_bias[col], b1 = s_bias[col + 1];
                float2* y0 = (float2*)(g_y + (size_t)r0 * HH + col);
                float2* y1 = (float2*)(g_y + (size_t)(r0 + 8) * HH + col);
                *y0 = make_float2(acc[mi][nf][0] + b0, acc[mi][nf][1] + b1);
                *y1 = make_float2(acc[mi][nf][2] + b0, acc[mi][nf][3] + b1);
            }
        }
    }
}

// ------------- gather + relu + bf16 split (R7) + optional counter re-zero --
__device__ __forceinline__ int segoff(int s) { return g_off[s] + g_bt2[s >> 10]; }

__global__ void __launch_bounds__(256) k_gather_relu(int zero_cnt) {
    int gtid = blockIdx.x * blockDim.x + threadIdx.x;
    if (zero_cnt && gtid < NSEG) { g_cnt[gtid] = 0; g_cur[gtid] = 0; }
    int node = gtid >> 5;
    int lane = threadIdx.x & 31;
    if (node >= NN) return;

    float4 acc = ((const float4*)(g_y + (size_t)node * HH))[lane];
    int st = segoff(node * RR);
#pragma unroll
    for (int r = 0; r < RR; r++) {
        int sn = node * RR + r + 1;
        int en = (sn < NSEG) ? segoff(sn) : EE;
        int cnt = en - st;
        if (cnt > 0) {
            float4 a = make_float4(0.f, 0.f, 0.f, 0.f);
            for (int j = st; j < en; j++) {
                int src = g_esrc[j];
                float4 z = *(const float4*)&g_z[(size_t)src * (RR * HH) + r * HH + lane * 4];
                a.x += z.x; a.y += z.y; a.z += z.z; a.w += z.w;
            }
            float sc = 1.0f / (float)cnt;
            acc.x += a.x * sc; acc.y += a.y * sc;
            acc.z += a.z * sc; acc.w += a.w * sc;
        }
        st = en;
    }
    acc.x = fmaxf(acc.x, 0.f); acc.y = fmaxf(acc.y, 0.f);
    acc.z = fmaxf(acc.z, 0.f); acc.w = fmaxf(acc.w, 0.f);

    ((float4*)(g_x + (size_t)node * HH))[lane] = acc;

    __nv_bfloat162 h0 = make_bfloat162(__float2bfloat16(acc.x), __float2bfloat16(acc.y));
    __nv_bfloat162 h1 = make_bfloat162(__float2bfloat16(acc.z), __float2bfloat16(acc.w));
    __nv_bfloat162 l0 = make_bfloat162(
        __float2bfloat16(acc.x - __bfloat162float(h0.x)),
        __float2bfloat16(acc.y - __bfloat162float(h0.y)));
    __nv_bfloat162 l1 = make_bfloat162(
        __float2bfloat16(acc.z - __bfloat162float(h1.x)),
        __float2bfloat16(acc.w - __bfloat162float(h1.y)));
    ((__nv_bfloat162*)(g_xhi + (size_t)node * HH))[lane * 2] = h0;
    ((__nv_bfloat162*)(g_xhi + (size_t)node * HH))[lane * 2 + 1] = h1;
    ((__nv_bfloat162*)(g_xlo + (size_t)node * HH))[lane * 2] = l0;
    ((__nv_bfloat162*)(g_xlo + (size_t)node * HH))[lane * 2 + 1] = l1;
}

// ---------------- seq transpose: [node, t] -> [b, t, node] -----------------
__global__ void __launch_bounds__(256) k_transp(const float* __restrict__ seq) {
    int b = blockIdx.x;
    __shared__ float s[NPG * LL];
    int tid = threadIdx.x;
    for (int idx = tid; idx < NPG * LL; idx += 256)
        s[idx] = seq[(size_t)b * NPG * LL + idx];
    __syncthreads();
    for (int idx = tid; idx < NPG * LL; idx += 256) {
        int t = idx >> 7, node = idx & 127;
        g_seqT[(size_t)b * LL * NPG + idx] = s[node * LL + t];
    }
}

// ---------------- pool + action head + sos (fused, block per graph) --------
__global__ void k_pool_action_sos(const int* __restrict__ nodes_bs,
                                  const float* __restrict__ wA, const float* __restrict__ bA,
                                  const float* __restrict__ wAf, const float* __restrict__ bAf,
                                  const int* __restrict__ act, const float* __restrict__ embA,
                                  float* __restrict__ out) {
    int b = blockIdx.x, o = threadIdx.x;
    __shared__ float sg[HH], t1[HH];
    float s = 0.f;
    const float* xp = g_x + (size_t)b * NPG * HH + o;
#pragma unroll 4
    for (int j = 0; j < NPG; j++) s += xp[j * HH];
    s /= (float)nodes_bs[b];
    g_hG[b * HH + o] = s;
    sg[o] = s;
    g_seqin[(size_t)b * LL * HH + o] = embA[act[b] * HH + o];
    __syncthreads();
    float acc = bA[o];
    const float* w = wA + o * HH;
#pragma unroll 8
    for (int h = 0; h < HH; h += 4) {
        float4 w4 = *(const float4*)&w[h];
        acc += sg[h] * w4.x + sg[h + 1] * w4.y + sg[h + 2] * w4.z + sg[h + 3] * w4.w;
    }
    t1[o] = fmaxf(acc, 0.f);
    __syncthreads();
    if (o < VAC) {
        float a2 = bAf[o];
        const float* w2 = wAf + o * HH;
#pragma unroll 8
        for (int h = 0; h < HH; h += 4) {
            float4 w4 = *(const float4*)&w2[h];
            a2 += t1[h] * w4.x + t1[h + 1] * w4.y + t1[h + 2] * w4.z + t1[h + 3] * w4.w;
        }
        out[b * VAC + o] = a2;
    }
}

// ---------------- GRU input assembly (coalesced via g_seqT) ----------------
__global__ void k_seqemb() {
    int t = blockIdx.x;
    int b = blockIdx.y;
    int h = threadIdx.x;
    __shared__ float s[NPG];
    s[h] = g_seqT[((size_t)b * LL + t) * NPG + h];
    __syncthreads();
    float acc = 0.f;
    for (int j = 0; j < NPG; j++) {
        float sv = s[j];
        if (sv != 0.0f)
            acc += sv * g_x[(size_t)(b * NPG + j) * HH + h];
    }
    g_seqin[((size_t)b * LL + t + 1) * HH + h] = acc;
}

// ---------------- generic C[m,j] = dot(X[m,:], W[j, woff:woff+128]) + bias -
__global__ void k_gemmT(const float* __restrict__ X, const float* __restrict__ W,
                        int ldw, int woff, const float* __restrict__ bias,
                        float* __restrict__ out) {
    int m0 = blockIdx.x * 16;
    int j = threadIdx.x;
    int J = blockDim.x;
    __shared__ float Xs[16 * HH];
    for (int idx = j; idx < 16 * HH; idx += J) Xs[idx] = X[(size_t)m0 * HH + idx];
    __syncthreads();
    float acc[16];
    float bv = bias ? bias[j] : 0.f;
#pragma unroll
    for (int m = 0; m < 16; m++) acc[m] = bv;
    const float* wr = W + (size_t)j * ldw + woff;
    for (int h = 0; h < HH; h += 4) {
        float4 w4 = *(const float4*)&wr[h];
#pragma unroll
        for (int m = 0; m < 16; m++) {
            acc[m] += Xs[m * HH + h] * w4.x;
            acc[m] += Xs[m * HH + h + 1] * w4.y;
            acc[m] += Xs[m * HH + h + 2] * w4.z;
            acc[m] += Xs[m * HH + h + 3] * w4.w;
        }
    }
#pragma unroll
    for (int m = 0; m < 16; m++) out[(size_t)(m0 + m) * J + j] = acc[m];
}

// node-head A and C in one grid (R10)
__global__ void k_gemmT_AC(const float* __restrict__ W, const float* __restrict__ biasN) {
    int bx = blockIdx.x;
    const float* X;
    const float* bias;
    int woff;
    float* out;
    int m0;
    if (bx < (BB * LL) / 16) {
        X = g_seqout; woff = 0; bias = nullptr; out = g_A; m0 = bx * 16;
    } else {
        X = g_x; woff = HH; bias = biasN; out = g_C; m0 = (bx - (BB * LL) / 16) * 16;
    }
    int j = threadIdx.x;
    __shared__ float Xs[16 * HH];
    for (int idx = j; idx < 16 * HH; idx += HH) Xs[idx] = X[(size_t)m0 * HH + idx];
    __syncthreads();
    float acc[16];
    float bv = bias ? bias[j] : 0.f;
#pragma unroll
    for (int m = 0; m < 16; m++) acc[m] = bv;
    const float* wr = W + (size_t)j * (2 * HH) + woff;
    for (int h = 0; h < HH; h += 4) {
        float4 w4 = *(const float4*)&wr[h];
#pragma unroll
        for (int m = 0; m < 16; m++) {
            acc[m] += Xs[m * HH + h] * w4.x;
            acc[m] += Xs[m * HH + h + 1] * w4.y;
            acc[m] += Xs[m * HH + h + 2] * w4.z;
            acc[m] += Xs[m * HH + h + 3] * w4.w;
        }
    }
#pragma unroll
    for (int m = 0; m < 16; m++) out[(size_t)(m0 + m) * HH + j] = acc[m];
}

// ---------------- GRU scan (float4 smem reads, R7 version) ----------------
__global__ void __launch_bounds__(384) k_gru(const float* __restrict__ w_hh,
                                             const float* __restrict__ b_hh,
                                             const int* __restrict__ len_seq) {
    int b = blockIdx.x;
    int g = threadIdx.x;
    __shared__ __align__(16) float sh[HH];
    __shared__ float sg[3 * HH];
    if (g < HH) sh[g] = g_hG[b * HH + g];
    int ls = len_seq[b];
    const float* w = w_hh + (size_t)g * HH;
    float bg = b_hh[g];
    __syncthreads();
    const float4* sh4 = (const float4*)sh;
    for (int t = 0; t < LL; t++) {
        float acc = bg;
#pragma unroll
        for (int k = 0; k < HH / 4; k++) {
            float4 w4 = *(const float4*)&w[k * 4];
            float4 h4 = sh4[k];
            acc += h4.x * w4.x + h4.y * w4.y + h4.z * w4.z + h4.w * w4.w;
        }
        sg[g] = acc;
        __syncthreads();
        if (g < HH) {
            const float* xwp = g_xw + ((size_t)b * LL + t) * (3 * HH);
            float rg = 1.f / (1.f + expf(-(xwp[g] + sg[g])));
            float zg = 1.f / (1.f + expf(-(xwp[HH + g] + sg[HH + g])));
            float ng = tanhf(xwp[2 * HH + g] + rg * sg[2 * HH + g]);
            float hnew = (1.f - zg) * ng + zg * sh[g];
            g_seqout[((size_t)b * LL + t) * HH + g] = (t < ls) ? hnew : 0.f;
            sh[g] = hnew;
        }
        __syncthreads();
    }
}

// ------- blocked node logits: 4 blocks per graph, A[b] staged in smem ------
__global__ void __launch_bounds__(256) k_logitsB(const float* __restrict__ wf,
                                                 const float* __restrict__ bf,
                                                 float* __restrict__ outN) {
    int b = blockIdx.x >> 2;
    int ng = blockIdx.x & 3;
    __shared__ float As[LL * HH];
    int tid = threadIdx.x, w = tid >> 5, lane = tid & 31;
    for (int idx = tid; idx < LL * HH; idx += 256)
        As[idx] = g_A[(size_t)b * LL * HH + idx];
    __syncthreads();
    float4 w4 = *(const float4*)&wf[lane * 4];
    float bias = bf[0];
#pragma unroll
    for (int k = 0; k < 4; k++) {
        int node = ng * 32 + w + 8 * k;
        int i = b * NPG + node;
        float4 c4 = *(const float4*)&g_C[(size_t)i * HH + lane * 4];
        for (int t0 = 0; t0 < LL; t0 += 4) {
            float s[4];
#pragma unroll
            for (int q = 0; q < 4; q++) {
                float4 a4 = *(const float4*)&As[(t0 + q) * HH + lane * 4];
                s[q] = fmaxf(a4.x + c4.x, 0.f) * w4.x
                     + fmaxf(a4.y + c4.y, 0.f) * w4.y
                     + fmaxf(a4.z + c4.z, 0.f) * w4.z
                     + fmaxf(a4.w + c4.w, 0.f) * w4.w;
            }
#pragma unroll
            for (int off = 16; off; off >>= 1) {
#pragma unroll
                for (int q = 0; q < 4; q++)
                    s[q] += __shfl_down_sync(0xffffffffu, s[q], off);
            }
            if (lane == 0) {
#pragma unroll
                for (int q = 0; q < 4; q++)
                    outN[(size_t)i * LL + t0 + q] = s[q] + bias;
            }
        }
    }
}

// ---------------- per-graph softmax, coalesced (R10) -----------------------
__global__ void __launch_bounds__(256) k_softmax2(float* __restrict__ outN) {
    int b = blockIdx.x;
    __shared__ float sm[LL * 129];
    __shared__ float smax[LL], ssum[LL];
    int tid = threadIdx.x;
    float* base = outN + (size_t)b * NPG * LL;

    for (int idx = tid; idx < NPG * LL; idx += 256) {
        int node = idx / LL, t = idx % LL;
        sm[t * 129 + node] = base[idx];
    }
    __syncthreads();

    int w = tid >> 5, lane = tid & 31;
    for (int t = w; t < LL; t += 8) {
        float v0 = sm[t * 129 + lane];
        float v1 = sm[t * 129 + lane + 32];
        float v2 = sm[t * 129 + lane + 64];
        float v3 = sm[t * 129 + lane + 96];
        float mx = fmaxf(fmaxf(v0, v1), fmaxf(v2, v3));
#pragma unroll
        for (int off = 16; off; off >>= 1)
            mx = fmaxf(mx, __shfl_xor_sync(0xffffffffu, mx, off));
        float e = expf(v0 - mx) + expf(v1 - mx) + expf(v2 - mx) + expf(v3 - mx);
#pragma unroll
        for (int off = 16; off; off >>= 1) e += __shfl_xor_sync(0xffffffffu, e, off);
        if (lane == 0) { smax[t] = mx; ssum[t] = e; }
    }
    __syncthreads();

    for (int idx = tid; idx < NPG * LL; idx += 256) {
        int node = idx / LL, t = idx % LL;
        base[idx] = expf(sm[t * 129 + node] - smax[t]) / ssum[t];
    }
}

// ---------------- launch ----------------
extern "C" void kernel_launch(void* const* d_in, const int* in_sizes, int n_in,
                              void* d_out, int out_size) {
    const int* nodeTypes   = (const int*)d_in[0];
    const int* edge_index  = (const int*)d_in[1];
    const int* edge_attr   = (const int*)d_in[2];
    const int* bs          = (const int*)d_in[3];
    const int* nodes_bs    = (const int*)d_in[4];
    const int* len_seq     = (const int*)d_in[5];
    const float* seq       = (const float*)d_in[6];
    const int* action_in   = (const int*)d_in[7];
    const float* emb_nodes = (const float*)d_in[8];
    const float* emb_act   = (const float*)d_in[9];
    const float* rgcn_rel  = (const float*)d_in[10];
    const float* rgcn_root = (const float*)d_in[11];
    const float* rgcn_bias = (const float*)d_in[12];
    const float* gru_w_ih  = (const float*)d_in[13];
    const float* gru_w_hh  = (const float*)d_in[14];
    const float* gru_b_ih  = (const float*)d_in[15];
    const float* gru_b_hh  = (const float*)d_in[16];
    const float* linA_w    = (const float*)d_in[17];
    const float* linA_b    = (const float*)d_in[18];
    const float* linAf_w   = (const float*)d_in[19];
    const float* linAf_b   = (const float*)d_in[20];
    const float* linN_w    = (const float*)d_in[21];
    const float* linN_b    = (const float*)d_in[22];
    const float* linNf_w   = (const float*)d_in[23];
    const float* linNf_b   = (const float*)d_in[24];

    float* out_action = (float*)d_out;
    float* out_nodes  = out_action + BB * VAC;

    float *p_seqin, *p_xw;
    cudaGetSymbolAddress((void**)&p_seqin, g_seqin);
    cudaGetSymbolAddress((void**)&p_xw, g_xw);

    cudaFuncSetAttribute(k_rgcn_mma, cudaFuncAttributeMaxDynamicSharedMemorySize, RGCN_SMEM);

    // 1: embed+count  2: convw  3: scan1  4: MMA li=0 (profiled slot)
    k_embed_split<<<(NN * HH) / 256, 256>>>(nodeTypes, emb_nodes, edge_index, edge_attr);
    k_convw<<<dim3(16, 27), 256>>>(rgcn_rel, rgcn_root);
    k_scan1<<<64, 1024>>>();
    k_rgcn_mma<<<dim3(9, 64), 512, RGCN_SMEM>>>(rgcn_bias, 0);

    k_scan2<<<1, 64>>>();
    k_scatter<<<EE / 256, 256>>>(edge_index, edge_attr);

    k_gather_relu<<<NN / 8, 256>>>(1);     // re-zeroes g_cnt/g_cur for next replay
    for (int li = 1; li < 3; li++) {
        k_rgcn_mma<<<dim3(9, 64), 512, RGCN_SMEM>>>(rgcn_bias, li);
        k_gather_relu<<<NN / 8, 256>>>(0);
    }

    k_transp<<<BB, 256>>>(seq);
    k_pool_action_sos<<<BB, HH>>>(nodes_bs, linA_w, linA_b, linAf_w, linAf_b,
                                  action_in, emb_act, out_action);
    k_seqemb<<<dim3(LL - 1, BB), NPG>>>();

    k_gemmT<<<(BB * LL) / 16, 3 * HH>>>(p_seqin, gru_w_ih, HH, 0, gru_b_ih, p_xw);
    k_gru<<<BB, 3 * HH>>>(gru_w_hh, gru_b_hh, len_seq);

    k_gemmT_AC<<<(BB * LL) / 16 + NN / 16, HH>>>(linN_w, linN_b);
    k_logitsB<<<BB * 4, 256>>>(linNf_w, linNf_b, out_nodes);
    k_softmax2<<<BB, 256>>>(out_nodes);
}

// round 13
// speedup vs baseline: 1.0580x; 1.0143x over previous
#include <cuda_runtime.h>
#include <cuda_bf16.h>
#include <math.h>
#include <stdint.h>

#define NN 8192
#define HH 128
#define RR 8
#define BB 64
#define LL 48
#define EE 65536
#define VAC 64
#define NSEG (NN * RR)
#define NPG (NN / BB)

// ---------------- scratch (device globals; no allocation) ----------------
__device__ float g_x[NN * HH];
__device__ __nv_bfloat16 g_xhi[NN * HH];
__device__ __nv_bfloat16 g_xlo[NN * HH];
__device__ __nv_bfloat16 g_wthi[27 * HH * HH];
__device__ __nv_bfloat16 g_wtlo[27 * HH * HH];
__device__ float g_y[NN * HH];
__device__ float g_z[NN * RR * HH];
__device__ int g_cnt[NSEG];                // zero at init; re-zeroed by gather#1
__device__ int g_cur[NSEG];
__device__ int g_off[NSEG];
__device__ int g_bt[64];
__device__ int g_bt2[64];
__device__ int g_esrc[EE];
__device__ float g_hG[BB * HH];
__device__ float g_seqin[BB * LL * HH];
__device__ float g_xw[BB * LL * 3 * HH];
__device__ float g_seqout[BB * LL * HH];
__device__ float g_A[BB * LL * HH];
__device__ float g_C[NN * HH];

__device__ __forceinline__ uint32_t smem_u32(const void* p) {
    uint32_t a;
    asm("{ .reg .u64 t; cvta.to.shared.u64 t, %1; cvt.u32.u64 %0, t; }" : "=r"(a) : "l"(p));
    return a;
}

// ---------------- embed + bf16 split + edge count (fused) ------------------
__global__ void k_embed_split(const int* __restrict__ nt, const float* __restrict__ emb,
                              const int* __restrict__ ei, const int* __restrict__ ea) {
    int i = blockIdx.x * blockDim.x + threadIdx.x;
    if (i < EE) atomicAdd(&g_cnt[ei[EE + i] * RR + ea[i]], 1);
    float v = emb[nt[i >> 7] * HH + (i & 127)];
    g_x[i] = v;
    __nv_bfloat16 hi = __float2bfloat16(v);
    g_xhi[i] = hi;
    g_xlo[i] = __float2bfloat16(v - __bfloat162float(hi));
}

// ---------------- CSR build: 2-level scan + scatter ----------------
__global__ void __launch_bounds__(1024) k_scan1() {
    __shared__ int s[1024];
    int i = blockIdx.x * 1024 + threadIdx.x;
    int v = g_cnt[i];
    s[threadIdx.x] = v;
    __syncthreads();
#pragma unroll
    for (int off = 1; off < 1024; off <<= 1) {
        int t = (threadIdx.x >= off) ? s[threadIdx.x - off] : 0;
        __syncthreads();
        s[threadIdx.x] += t;
        __syncthreads();
    }
    g_off[i] = s[threadIdx.x] - v;
    if (threadIdx.x == 1023) g_bt[blockIdx.x] = s[1023];
}
__global__ void k_scan2() {
    __shared__ int s[64];
    int v = g_bt[threadIdx.x];
    s[threadIdx.x] = v;
    __syncthreads();
#pragma unroll
    for (int off = 1; off < 64; off <<= 1) {
        int t = (threadIdx.x >= off) ? s[threadIdx.x - off] : 0;
        __syncthreads();
        s[threadIdx.x] += t;
        __syncthreads();
    }
    g_bt2[threadIdx.x] = s[threadIdx.x] - v;
}
__global__ void k_scatter(const int* __restrict__ ei, const int* __restrict__ ea) {
    int e = blockIdx.x * blockDim.x + threadIdx.x;
    if (e >= EE) return;
    int seg = ei[EE + e] * RR + ea[e];
    int pos = g_off[seg] + g_bt2[seg >> 10] + atomicAdd(&g_cur[seg], 1);
    g_esrc[pos] = ei[e];
}

// ---------------- weight transpose + split (smem-tiled) --------------------
__global__ void k_convw(const float* __restrict__ rel, const float* __restrict__ root) {
    __shared__ float ts[32][33];
    int w = blockIdx.y;
    int li = w / 9, cb = w % 9;
    const float* W = (cb < 8) ? rel + (size_t)(li * 8 + cb) * (HH * HH)
                              : root + (size_t)li * (HH * HH);
    int tx = (blockIdx.x & 3) * 32;
    int ty = (blockIdx.x >> 2) * 32;
    int r = threadIdx.x >> 5;
    int c = threadIdx.x & 31;
#pragma unroll
    for (int i = 0; i < 32; i += 8)
        ts[r + i][c] = W[(size_t)(ty + r + i) * HH + tx + c];
    __syncthreads();
    size_t base = (size_t)w * HH * HH;
#pragma unroll
    for (int i = 0; i < 32; i += 8) {
        float v = ts[c][r + i];
        __nv_bfloat16 hi = __float2bfloat16(v);
        size_t p = base + (size_t)(tx + r + i) * HH + ty + c;
        g_wthi[p] = hi;
        g_wtlo[p] = __float2bfloat16(v - __bfloat162float(hi));
    }
}

// ====== RGCN GEMM: mma.sync bf16, 128-row tiles, 512 thr, 4Mx4N ============
#define LDT 136
#define TILE_B (128 * LDT * 2)
#define RGCN_SMEM (4 * TILE_B)

#define MMA16816(d, a0, a1, a2, a3, b0, b1)                                 \
    asm volatile("mma.sync.aligned.m16n8k16.row.col.f32.bf16.bf16.f32 "     \
                 "{%0,%1,%2,%3}, {%4,%5,%6,%7}, {%8,%9}, {%0,%1,%2,%3};"    \
                 : "+f"((d)[0]), "+f"((d)[1]), "+f"((d)[2]), "+f"((d)[3])   \
                 : "r"(a0), "r"(a1), "r"(a2), "r"(a3), "r"(b0), "r"(b1))

#define LDMX4(r0, r1, r2, r3, addr)                                         \
    asm volatile("ldmatrix.sync.aligned.m8n8.x4.shared.b16 {%0,%1,%2,%3}, [%4];" \
                 : "=r"(r0), "=r"(r1), "=r"(r2), "=r"(r3) : "r"(addr))

__global__ void __launch_bounds__(512) k_rgcn_mma(const float* __restrict__ bias, int li) {
    extern __shared__ char sm[];
    __shared__ float s_bias[HH];

    int tid = threadIdx.x;
    int cb = blockIdx.x, mb = blockIdx.y;
    int m0 = mb * 128;
    int widx = li * 9 + cb;

    if (cb == 8 && tid < HH) s_bias[tid] = bias[li * HH + tid];

    {
        const uint4* srcs[4] = {
            (const uint4*)(g_xhi + (size_t)m0 * HH),
            (const uint4*)(g_xlo + (size_t)m0 * HH),
            (const uint4*)(g_wthi + (size_t)widx * HH * HH),
            (const uint4*)(g_wtlo + (size_t)widx * HH * HH)};
#pragma unroll
        for (int ti = 0; ti < 4; ti++) {
            const uint4* src = srcs[ti];
            char* dst = sm + ti * TILE_B;
#pragma unroll
            for (int t = 0; t < 4; t++) {
                int c = tid + t * 512;
                int r = c >> 4, q = c & 15;
                *(uint4*)(dst + r * (LDT * 2) + q * 16) = src[r * 16 + q];
            }
        }
    }
    __syncthreads();

    int lane = tid & 31, wid = tid >> 5;
    int warpM = wid & 3;
    int warpN = wid >> 2;
    int g = lane >> 2, tg = lane & 3;

    uint32_t smbase = smem_u32(sm);
    uint32_t aOff = (uint32_t)((warpM * 32 + (lane & 15)) * LDT + ((lane & 16) ? 8 : 0)) * 2;
    uint32_t bOff = (uint32_t)((warpN * 32 + (lane & 7) + ((lane & 16) ? 8 : 0)) * LDT +
                               ((lane & 8) ? 8 : 0)) * 2;

    uint32_t aH = smbase + aOff;
    uint32_t aL = smbase + TILE_B + aOff;
    uint32_t bH = smbase + 2 * TILE_B + bOff;
    uint32_t bL = smbase + 3 * TILE_B + bOff;

    float acc[2][4][4];
#pragma unroll
    for (int mi = 0; mi < 2; mi++)
#pragma unroll
        for (int nf = 0; nf < 4; nf++)
#pragma unroll
            for (int j = 0; j < 4; j++) acc[mi][nf][j] = 0.f;

#pragma unroll
    for (int kc = 0; kc < 8; kc++) {
        uint32_t kb = kc * 32;
        uint32_t ah[2][4], al[2][4];
        LDMX4(ah[0][0], ah[0][1], ah[0][2], ah[0][3], aH + kb);
        LDMX4(ah[1][0], ah[1][1], ah[1][2], ah[1][3], aH + 16 * LDT * 2 + kb);
        LDMX4(al[0][0], al[0][1], al[0][2], al[0][3], aL + kb);
        LDMX4(al[1][0], al[1][1], al[1][2], al[1][3], aL + 16 * LDT * 2 + kb);
#pragma unroll
        for (int p = 0; p < 2; p++) {
            uint32_t bh0, bh1, bh2, bh3, bl0, bl1, bl2, bl3;
            LDMX4(bh0, bh1, bh2, bh3, bH + p * (16 * LDT * 2) + kb);
            LDMX4(bl0, bl1, bl2, bl3, bL + p * (16 * LDT * 2) + kb);
#pragma unroll
            for (int mi = 0; mi < 2; mi++) {
                MMA16816(acc[mi][2 * p],     ah[mi][0], ah[mi][1], ah[mi][2], ah[mi][3], bh0, bh1);
                MMA16816(acc[mi][2 * p + 1], ah[mi][0], ah[mi][1], ah[mi][2], ah[mi][3], bh2, bh3);
                MMA16816(acc[mi][2 * p],     ah[mi][0], ah[mi][1], ah[mi][2], ah[mi][3], bl0, bl1);
                MMA16816(acc[mi][2 * p + 1], ah[mi][0], ah[mi][1], ah[mi][2], ah[mi][3], bl2, bl3);
                MMA16816(acc[mi][2 * p],     al[mi][0], al[mi][1], al[mi][2], al[mi][3], bh0, bh1);
                MMA16816(acc[mi][2 * p + 1], al[mi][0], al[mi][1], al[mi][2], al[mi][3], bh2, bh3);
            }
        }
    }

#pragma unroll
    for (int mi = 0; mi < 2; mi++) {
        int r0 = m0 + warpM * 32 + mi * 16 + g;
#pragma unroll
        for (int nf = 0; nf < 4; nf++) {
            int col = warpN * 32 + nf * 8 + tg * 2;
            if (cb < 8) {
                float2* z0 = (float2*)(g_z + (size_t)r0 * (RR * HH) + cb * HH + col);
                float2* z1 = (float2*)(g_z + (size_t)(r0 + 8) * (RR * HH) + cb * HH + col);
                *z0 = make_float2(acc[mi][nf][0], acc[mi][nf][1]);
                *z1 = make_float2(acc[mi][nf][2], acc[mi][nf][3]);
            } else {
                float b0 = s_bias[col], b1 = s_bias[col + 1];
                float2* y0 = (float2*)(g_y + (size_t)r0 * HH + col);
                float2* y1 = (float2*)(g_y + (size_t)(r0 + 8) * HH + col);
                *y0 = make_float2(acc[mi][nf][0] + b0, acc[mi][nf][1] + b1);
                *y1 = make_float2(acc[mi][nf][2] + b0, acc[mi][nf][3] + b1);
            }
        }
    }
}

// ------------- gather + relu + bf16 split (R7) + optional counter re-zero --
__device__ __forceinline__ int segoff(int s) { return g_off[s] + g_bt2[s >> 10]; }

__global__ void __launch_bounds__(256) k_gather_relu(int zero_cnt) {
    int gtid = blockIdx.x * blockDim.x + threadIdx.x;
    if (zero_cnt && gtid < NSEG) { g_cnt[gtid] = 0; g_cur[gtid] = 0; }
    int node = gtid >> 5;
    int lane = threadIdx.x & 31;
    if (node >= NN) return;

    float4 acc = ((const float4*)(g_y + (size_t)node * HH))[lane];
    int st = segoff(node * RR);
#pragma unroll
    for (int r = 0; r < RR; r++) {
        int sn = node * RR + r + 1;
        int en = (sn < NSEG) ? segoff(sn) : EE;
        int cnt = en - st;
        if (cnt > 0) {
            float4 a = make_float4(0.f, 0.f, 0.f, 0.f);
            for (int j = st; j < en; j++) {
                int src = g_esrc[j];
                float4 z = *(const float4*)&g_z[(size_t)src * (RR * HH) + r * HH + lane * 4];
                a.x += z.x; a.y += z.y; a.z += z.z; a.w += z.w;
            }
            float sc = 1.0f / (float)cnt;
            acc.x += a.x * sc; acc.y += a.y * sc;
            acc.z += a.z * sc; acc.w += a.w * sc;
        }
        st = en;
    }
    acc.x = fmaxf(acc.x, 0.f); acc.y = fmaxf(acc.y, 0.f);
    acc.z = fmaxf(acc.z, 0.f); acc.w = fmaxf(acc.w, 0.f);

    ((float4*)(g_x + (size_t)node * HH))[lane] = acc;

    __nv_bfloat162 h0 = make_bfloat162(__float2bfloat16(acc.x), __float2bfloat16(acc.y));
    __nv_bfloat162 h1 = make_bfloat162(__float2bfloat16(acc.z), __float2bfloat16(acc.w));
    __nv_bfloat162 l0 = make_bfloat162(
        __float2bfloat16(acc.x - __bfloat162float(h0.x)),
        __float2bfloat16(acc.y - __bfloat162float(h0.y)));
    __nv_bfloat162 l1 = make_bfloat162(
        __float2bfloat16(acc.z - __bfloat162float(h1.x)),
        __float2bfloat16(acc.w - __bfloat162float(h1.y)));
    ((__nv_bfloat162*)(g_xhi + (size_t)node * HH))[lane * 2] = h0;
    ((__nv_bfloat162*)(g_xhi + (size_t)node * HH))[lane * 2 + 1] = h1;
    ((__nv_bfloat162*)(g_xlo + (size_t)node * HH))[lane * 2] = l0;
    ((__nv_bfloat162*)(g_xlo + (size_t)node * HH))[lane * 2 + 1] = l1;
}

// ---------------- pool + action head + sos (fused, block per graph) --------
__global__ void k_pool_action_sos(const int* __restrict__ nodes_bs,
                                  const float* __restrict__ wA, const float* __restrict__ bA,
                                  const float* __restrict__ wAf, const float* __restrict__ bAf,
                                  const int* __restrict__ act, const float* __restrict__ embA,
                                  float* __restrict__ out) {
    int b = blockIdx.x, o = threadIdx.x;
    __shared__ float sg[HH], t1[HH];
    float s = 0.f;
    const float* xp = g_x + (size_t)b * NPG * HH + o;
#pragma unroll 4
    for (int j = 0; j < NPG; j++) s += xp[j * HH];
    s /= (float)nodes_bs[b];
    g_hG[b * HH + o] = s;
    sg[o] = s;
    g_seqin[(size_t)b * LL * HH + o] = embA[act[b] * HH + o];
    __syncthreads();
    float acc = bA[o];
    const float* w = wA + o * HH;
#pragma unroll 8
    for (int h = 0; h < HH; h += 4) {
        float4 w4 = *(const float4*)&w[h];
        acc += sg[h] * w4.x + sg[h + 1] * w4.y + sg[h + 2] * w4.z + sg[h + 3] * w4.w;
    }
    t1[o] = fmaxf(acc, 0.f);
    __syncthreads();
    if (o < VAC) {
        float a2 = bAf[o];
        const float* w2 = wAf + o * HH;
#pragma unroll 8
        for (int h = 0; h < HH; h += 4) {
            float4 w4 = *(const float4*)&w2[h];
            a2 += t1[h] * w4.x + t1[h + 1] * w4.y + t1[h + 2] * w4.z + t1[h + 3] * w4.w;
        }
        out[b * VAC + o] = a2;
    }
}

// ---------------- GRU input assembly (R10) ----------------
__global__ void k_seqemb(const float* __restrict__ seq) {
    int t = blockIdx.x;
    int b = blockIdx.y;
    int h = threadIdx.x;
    __shared__ float s[NPG];
    s[h] = seq[(size_t)(b * NPG + h) * LL + t];
    __syncthreads();
    float acc = 0.f;
    for (int j = 0; j < NPG; j++) {
        float sv = s[j];
        if (sv != 0.0f)
            acc += sv * g_x[(size_t)(b * NPG + j) * HH + h];
    }
    g_seqin[((size_t)b * LL + t + 1) * HH + h] = acc;
}

// ---------------- generic C[m,j] = dot(X[m,:], W[j, woff:woff+128]) + bias -
__global__ void k_gemmT(const float* __restrict__ X, const float* __restrict__ W,
                        int ldw, int woff, const float* __restrict__ bias,
                        float* __restrict__ out) {
    int m0 = blockIdx.x * 16;
    int j = threadIdx.x;
    int J = blockDim.x;
    __shared__ float Xs[16 * HH];
    for (int idx = j; idx < 16 * HH; idx += J) Xs[idx] = X[(size_t)m0 * HH + idx];
    __syncthreads();
    float acc[16];
    float bv = bias ? bias[j] : 0.f;
#pragma unroll
    for (int m = 0; m < 16; m++) acc[m] = bv;
    const float* wr = W + (size_t)j * ldw + woff;
    for (int h = 0; h < HH; h += 4) {
        float4 w4 = *(const float4*)&wr[h];
#pragma unroll
        for (int m = 0; m < 16; m++) {
            acc[m] += Xs[m * HH + h] * w4.x;
            acc[m] += Xs[m * HH + h + 1] * w4.y;
            acc[m] += Xs[m * HH + h + 2] * w4.z;
            acc[m] += Xs[m * HH + h + 3] * w4.w;
        }
    }
#pragma unroll
    for (int m = 0; m < 16; m++) out[(size_t)(m0 + m) * J + j] = acc[m];
}

// node-head A and C in one grid (R10)
__global__ void k_gemmT_AC(const float* __restrict__ W, const float* __restrict__ biasN) {
    int bx = blockIdx.x;
    const float* X;
    const float* bias;
    int woff;
    float* out;
    int m0;
    if (bx < (BB * LL) / 16) {
        X = g_seqout; woff = 0; bias = nullptr; out = g_A; m0 = bx * 16;
    } else {
        X = g_x; woff = HH; bias = biasN; out = g_C; m0 = (bx - (BB * LL) / 16) * 16;
    }
    int j = threadIdx.x;
    __shared__ float Xs[16 * HH];
    for (int idx = j; idx < 16 * HH; idx += HH) Xs[idx] = X[(size_t)m0 * HH + idx];
    __syncthreads();
    float acc[16];
    float bv = bias ? bias[j] : 0.f;
#pragma unroll
    for (int m = 0; m < 16; m++) acc[m] = bv;
    const float* wr = W + (size_t)j * (2 * HH) + woff;
    for (int h = 0; h < HH; h += 4) {
        float4 w4 = *(const float4*)&wr[h];
#pragma unroll
        for (int m = 0; m < 16; m++) {
            acc[m] += Xs[m * HH + h] * w4.x;
            acc[m] += Xs[m * HH + h + 1] * w4.y;
            acc[m] += Xs[m * HH + h + 2] * w4.z;
            acc[m] += Xs[m * HH + h + 3] * w4.w;
        }
    }
#pragma unroll
    for (int m = 0; m < 16; m++) out[(size_t)(m0 + m) * HH + j] = acc[m];
}

// ---------------- GRU scan: register-resident weights (384 thr) ------------
__global__ void __launch_bounds__(384, 1) k_gru(const float* __restrict__ w_hh,
                                                const float* __restrict__ b_hh,
                                                const int* __restrict__ len_seq) {
    int b = blockIdx.x;
    int g = threadIdx.x;
    __shared__ __align__(16) float sh[HH];
    __shared__ float sg[3 * HH];

    float4 w[32];
    const float4* wp = (const float4*)(w_hh + (size_t)g * HH);
#pragma unroll
    for (int k = 0; k < 32; k++) w[k] = wp[k];
    float bg = b_hh[g];
    if (g < HH) sh[g] = g_hG[b * HH + g];
    int ls = len_seq[b];
    __syncthreads();

    const float4* sh4 = (const float4*)sh;
    for (int t = 0; t < LL; t++) {
        float a0 = 0.f, a1 = 0.f, a2 = 0.f, a3 = 0.f;
#pragma unroll
        for (int k = 0; k < 32; k += 4) {
            float4 h0 = sh4[k], h1 = sh4[k + 1], h2 = sh4[k + 2], h3 = sh4[k + 3];
            a0 += h0.x * w[k].x + h0.y * w[k].y + h0.z * w[k].z + h0.w * w[k].w;
            a1 += h1.x * w[k + 1].x + h1.y * w[k + 1].y + h1.z * w[k + 1].z + h1.w * w[k + 1].w;
            a2 += h2.x * w[k + 2].x + h2.y * w[k + 2].y + h2.z * w[k + 2].z + h2.w * w[k + 2].w;
            a3 += h3.x * w[k + 3].x + h3.y * w[k + 3].y + h3.z * w[k + 3].z + h3.w * w[k + 3].w;
        }
        sg[g] = bg + (a0 + a1) + (a2 + a3);
        __syncthreads();
        if (g < HH) {
            const float* xwp = g_xw + ((size_t)b * LL + t) * (3 * HH);
            float rg = 1.f / (1.f + expf(-(xwp[g] + sg[g])));
            float zg = 1.f / (1.f + expf(-(xwp[HH + g] + sg[HH + g])));
            float ng = tanhf(xwp[2 * HH + g] + rg * sg[2 * HH + g]);
            float hnew = (1.f - zg) * ng + zg * sh[g];
            g_seqout[((size_t)b * LL + t) * HH + g] = (t < ls) ? hnew : 0.f;
            sh[g] = hnew;
        }
        __syncthreads();
    }
}

// ------- blocked node logits: 4 blocks per graph, A[b] staged in smem ------
__global__ void __launch_bounds__(256) k_logitsB(const float* __restrict__ wf,
                                                 const float* __restrict__ bf,
                                                 float* __restrict__ outN) {
    int b = blockIdx.x >> 2;
    int ng = blockIdx.x & 3;
    __shared__ float As[LL * HH];
    int tid = threadIdx.x, w = tid >> 5, lane = tid & 31;
    for (int idx = tid; idx < LL * HH; idx += 256)
        As[idx] = g_A[(size_t)b * LL * HH + idx];
    __syncthreads();
    float4 w4 = *(const float4*)&wf[lane * 4];
    float bias = bf[0];
#pragma unroll
    for (int k = 0; k < 4; k++) {
        int node = ng * 32 + w + 8 * k;
        int i = b * NPG + node;
        float4 c4 = *(const float4*)&g_C[(size_t)i * HH + lane * 4];
        for (int t0 = 0; t0 < LL; t0 += 4) {
            float s[4];
#pragma unroll
            for (int q = 0; q < 4; q++) {
                float4 a4 = *(const float4*)&As[(t0 + q) * HH + lane * 4];
                s[q] = fmaxf(a4.x + c4.x, 0.f) * w4.x
                     + fmaxf(a4.y + c4.y, 0.f) * w4.y
                     + fmaxf(a4.z + c4.z, 0.f) * w4.z
                     + fmaxf(a4.w + c4.w, 0.f) * w4.w;
            }
#pragma unroll
            for (int off = 16; off; off >>= 1) {
#pragma unroll
                for (int q = 0; q < 4; q++)
                    s[q] += __shfl_down_sync(0xffffffffu, s[q], off);
            }
            if (lane == 0) {
#pragma unroll
                for (int q = 0; q < 4; q++)
                    outN[(size_t)i * LL + t0 + q] = s[q] + bias;
            }
        }
    }
}

// ---------------- per-graph softmax, coalesced (R10) -----------------------
__global__ void __launch_bounds__(256) k_softmax2(float* __restrict__ outN) {
    int b = blockIdx.x;
    __shared__ float sm[LL * 129];
    __shared__ float smax[LL], ssum[LL];
    int tid = threadIdx.x;
    float* base = outN + (size_t)b * NPG * LL;

    for (int idx = tid; idx < NPG * LL; idx += 256) {
        int node = idx / LL, t = idx % LL;
        sm[t * 129 + node] = base[idx];
    }
    __syncthreads();

    int w = tid >> 5, lane = tid & 31;
    for (int t = w; t < LL; t += 8) {
        float v0 = sm[t * 129 + lane];
        float v1 = sm[t * 129 + lane + 32];
        float v2 = sm[t * 129 + lane + 64];
        float v3 = sm[t * 129 + lane + 96];
        float mx = fmaxf(fmaxf(v0, v1), fmaxf(v2, v3));
#pragma unroll
        for (int off = 16; off; off >>= 1)
            mx = fmaxf(mx, __shfl_xor_sync(0xffffffffu, mx, off));
        float e = expf(v0 - mx) + expf(v1 - mx) + expf(v2 - mx) + expf(v3 - mx);
#pragma unroll
        for (int off = 16; off; off >>= 1) e += __shfl_xor_sync(0xffffffffu, e, off);
        if (lane == 0) { smax[t] = mx; ssum[t] = e; }
    }
    __syncthreads();

    for (int idx = tid; idx < NPG * LL; idx += 256) {
        int node = idx / LL, t = idx % LL;
        base[idx] = expf(sm[t * 129 + node] - smax[t]) / ssum[t];
    }
}

// ---------------- launch ----------------
extern "C" void kernel_launch(void* const* d_in, const int* in_sizes, int n_in,
                              void* d_out, int out_size) {
    const int* nodeTypes   = (const int*)d_in[0];
    const int* edge_index  = (const int*)d_in[1];
    const int* edge_attr   = (const int*)d_in[2];
    const int* bs          = (const int*)d_in[3];
    const int* nodes_bs    = (const int*)d_in[4];
    const int* len_seq     = (const int*)d_in[5];
    const float* seq       = (const float*)d_in[6];
    const int* action_in   = (const int*)d_in[7];
    const float* emb_nodes = (const float*)d_in[8];
    const float* emb_act   = (const float*)d_in[9];
    const float* rgcn_rel  = (const float*)d_in[10];
    const float* rgcn_root = (const float*)d_in[11];
    const float* rgcn_bias = (const float*)d_in[12];
    const float* gru_w_ih  = (const float*)d_in[13];
    const float* gru_w_hh  = (const float*)d_in[14];
    const float* gru_b_ih  = (const float*)d_in[15];
    const float* gru_b_hh  = (const float*)d_in[16];
    const float* linA_w    = (const float*)d_in[17];
    const float* linA_b    = (const float*)d_in[18];
    const float* linAf_w   = (const float*)d_in[19];
    const float* linAf_b   = (const float*)d_in[20];
    const float* linN_w    = (const float*)d_in[21];
    const float* linN_b    = (const float*)d_in[22];
    const float* linNf_w   = (const float*)d_in[23];
    const float* linNf_b   = (const float*)d_in[24];

    float* out_action = (float*)d_out;
    float* out_nodes  = out_action + BB * VAC;

    float *p_seqin, *p_xw;
    cudaGetSymbolAddress((void**)&p_seqin, g_seqin);
    cudaGetSymbolAddress((void**)&p_xw, g_xw);

    cudaFuncSetAttribute(k_rgcn_mma, cudaFuncAttributeMaxDynamicSharedMemorySize, RGCN_SMEM);

    // 1: embed+count  2: convw  3: scan1  4: MMA li=0 (profiled slot)
    k_embed_split<<<(NN * HH) / 256, 256>>>(nodeTypes, emb_nodes, edge_index, edge_attr);
    k_convw<<<dim3(16, 27), 256>>>(rgcn_rel, rgcn_root);
    k_scan1<<<64, 1024>>>();
    k_rgcn_mma<<<dim3(9, 64), 512, RGCN_SMEM>>>(rgcn_bias, 0);

    k_scan2<<<1, 64>>>();
    k_scatter<<<EE / 256, 256>>>(edge_index, edge_attr);

    k_gather_relu<<<NN / 8, 256>>>(1);     // re-zeroes g_cnt/g_cur for next replay
    for (int li = 1; li < 3; li++) {
        k_rgcn_mma<<<dim3(9, 64), 512, RGCN_SMEM>>>(rgcn_bias, li);
        k_gather_relu<<<NN / 8, 256>>>(0);
    }

    k_pool_action_sos<<<BB, HH>>>(nodes_bs, linA_w, linA_b, linAf_w, linAf_b,
                                  action_in, emb_act, out_action);
    k_seqemb<<<dim3(LL - 1, BB), NPG>>>(seq);

    k_gemmT<<<(BB * LL) / 16, 3 * HH>>>(p_seqin, gru_w_ih, HH, 0, gru_b_ih, p_xw);
    k_gru<<<BB, 3 * HH>>>(gru_w_hh, gru_b_hh, len_seq);

    k_gemmT_AC<<<(BB * LL) / 16 + NN / 16, HH>>>(linN_w, linN_b);
    k_logitsB<<<BB * 4, 256>>>(linNf_w, linNf_b, out_nodes);
    k_softmax2<<<BB, 256>>>(out_nodes);
}

// round 14
// speedup vs baseline: 1.1970x; 1.1314x over previous
#include <cuda_runtime.h>
#include <cuda_bf16.h>
#include <math.h>
#include <stdint.h>

#define NN 8192
#define HH 128
#define RR 8
#define BB 64
#define LL 48
#define EE 65536
#define VAC 64
#define NSEG (NN * RR)
#define NPG (NN / BB)

// ---------------- scratch (device globals; no allocation) ----------------
__device__ float g_x[NN * HH];
__device__ __nv_bfloat16 g_xhi[NN * HH];
__device__ __nv_bfloat16 g_xlo[NN * HH];
__device__ __nv_bfloat16 g_wthi[32 * HH * HH];
__device__ __nv_bfloat16 g_wtlo[32 * HH * HH];
__device__ float g_y[NN * HH];
__device__ float g_z[NN * RR * HH];
__device__ int g_cnt[NSEG];                // zero at init; re-zeroed by gather#1
__device__ int g_cur[NSEG];
__device__ int g_off[NSEG];
__device__ int g_bt[64];
__device__ int g_bt2[64];
__device__ int g_esrc[EE];
__device__ float g_hG[BB * HH];
__device__ float g_seqin[BB * LL * HH];
__device__ __nv_bfloat16 g_sihi[BB * LL * HH];
__device__ __nv_bfloat16 g_silo[BB * LL * HH];
__device__ float g_xw[BB * LL * 3 * HH];
__device__ float g_seqout[BB * LL * HH];
__device__ __nv_bfloat16 g_sohi[BB * LL * HH];
__device__ __nv_bfloat16 g_solo[BB * LL * HH];
__device__ float g_A[BB * LL * HH];
__device__ float g_C[NN * HH];

__device__ __forceinline__ uint32_t smem_u32(const void* p) {
    uint32_t a;
    asm("{ .reg .u64 t; cvta.to.shared.u64 t, %1; cvt.u32.u64 %0, t; }" : "=r"(a) : "l"(p));
    return a;
}

// ---------------- embed + bf16 split + edge count (fused) ------------------
__global__ void k_embed_split(const int* __restrict__ nt, const float* __restrict__ emb,
                              const int* __restrict__ ei, const int* __restrict__ ea) {
    int i = blockIdx.x * blockDim.x + threadIdx.x;
    if (i < EE) atomicAdd(&g_cnt[ei[EE + i] * RR + ea[i]], 1);
    float v = emb[nt[i >> 7] * HH + (i & 127)];
    g_x[i] = v;
    __nv_bfloat16 hi = __float2bfloat16(v);
    g_xhi[i] = hi;
    g_xlo[i] = __float2bfloat16(v - __bfloat162float(hi));
}

// ---------------- CSR build: 2-level scan + scatter ----------------
__global__ void __launch_bounds__(1024) k_scan1() {
    __shared__ int s[1024];
    int i = blockIdx.x * 1024 + threadIdx.x;
    int v = g_cnt[i];
    s[threadIdx.x] = v;
    __syncthreads();
#pragma unroll
    for (int off = 1; off < 1024; off <<= 1) {
        int t = (threadIdx.x >= off) ? s[threadIdx.x - off] : 0;
        __syncthreads();
        s[threadIdx.x] += t;
        __syncthreads();
    }
    g_off[i] = s[threadIdx.x] - v;
    if (threadIdx.x == 1023) g_bt[blockIdx.x] = s[1023];
}
__global__ void k_scan2() {
    __shared__ int s[64];
    int v = g_bt[threadIdx.x];
    s[threadIdx.x] = v;
    __syncthreads();
#pragma unroll
    for (int off = 1; off < 64; off <<= 1) {
        int t = (threadIdx.x >= off) ? s[threadIdx.x - off] : 0;
        __syncthreads();
        s[threadIdx.x] += t;
        __syncthreads();
    }
    g_bt2[threadIdx.x] = s[threadIdx.x] - v;
}
__global__ void k_scatter(const int* __restrict__ ei, const int* __restrict__ ea) {
    int e = blockIdx.x * blockDim.x + threadIdx.x;
    if (e >= EE) return;
    int seg = ei[EE + e] * RR + ea[e];
    int pos = g_off[seg] + g_bt2[seg >> 10] + atomicAdd(&g_cur[seg], 1);
    g_esrc[pos] = ei[e];
}

// ------- weight prep: slots 0..26 transpose+split; 27..31 copy+split -------
// slot 27: linN_w[:,128:256]  28: linN_w[:,0:128]  29..31: gru_w_ih thirds
__global__ void k_convw(const float* __restrict__ rel, const float* __restrict__ root,
                        const float* __restrict__ linN, const float* __restrict__ wih) {
    int w = blockIdx.y;
    if (w < 27) {
        __shared__ float ts[32][33];
        int li = w / 9, cb = w % 9;
        const float* W = (cb < 8) ? rel + (size_t)(li * 8 + cb) * (HH * HH)
                                  : root + (size_t)li * (HH * HH);
        int tx = (blockIdx.x & 3) * 32;
        int ty = (blockIdx.x >> 2) * 32;
        int r = threadIdx.x >> 5;
        int c = threadIdx.x & 31;
#pragma unroll
        for (int i = 0; i < 32; i += 8)
            ts[r + i][c] = W[(size_t)(ty + r + i) * HH + tx + c];
        __syncthreads();
        size_t base = (size_t)w * HH * HH;
#pragma unroll
        for (int i = 0; i < 32; i += 8) {
            float v = ts[c][r + i];
            __nv_bfloat16 hi = __float2bfloat16(v);
            size_t p = base + (size_t)(tx + r + i) * HH + ty + c;
            g_wthi[p] = hi;
            g_wtlo[p] = __float2bfloat16(v - __bfloat162float(hi));
        }
    } else {
        size_t base = (size_t)w * HH * HH;
#pragma unroll
        for (int q = 0; q < 4; q++) {
            int idx = blockIdx.x * 1024 + threadIdx.x + q * 256;
            int n = idx >> 7, k = idx & 127;
            float v;
            if (w == 27) v = linN[(size_t)n * 256 + 128 + k];
            else if (w == 28) v = linN[(size_t)n * 256 + k];
            else v = wih[(size_t)(w - 29) * 16384 + idx];
            __nv_bfloat16 hi = __float2bfloat16(v);
            g_wthi[base + idx] = hi;
            g_wtlo[base + idx] = __float2bfloat16(v - __bfloat162float(hi));
        }
    }
}

// ====== shared HMMA tile body: out[128,128] = A[128,128] @ Wslot^T =========
#define LDT 136
#define TILE_B (128 * LDT * 2)
#define RGCN_SMEM (4 * TILE_B)

#define MMA16816(d, a0, a1, a2, a3, b0, b1)                                 \
    asm volatile("mma.sync.aligned.m16n8k16.row.col.f32.bf16.bf16.f32 "     \
                 "{%0,%1,%2,%3}, {%4,%5,%6,%7}, {%8,%9}, {%0,%1,%2,%3};"    \
                 : "+f"((d)[0]), "+f"((d)[1]), "+f"((d)[2]), "+f"((d)[3])   \
                 : "r"(a0), "r"(a1), "r"(a2), "r"(a3), "r"(b0), "r"(b1))

#define LDMX4(r0, r1, r2, r3, addr)                                         \
    asm volatile("ldmatrix.sync.aligned.m8n8.x4.shared.b16 {%0,%1,%2,%3}, [%4];" \
                 : "=r"(r0), "=r"(r1), "=r"(r2), "=r"(r3) : "r"(addr))

struct TileOut {
    float acc[2][4][4];
    int warpM, warpN, g, tg;
};

__device__ __forceinline__ void hmma_tile(char* sm,
                                          const __nv_bfloat16* Ahi, const __nv_bfloat16* Alo,
                                          int m0, int ws, TileOut& o) {
    int tid = threadIdx.x;
    {
        const uint4* srcs[4] = {
            (const uint4*)(Ahi + (size_t)m0 * HH),
            (const uint4*)(Alo + (size_t)m0 * HH),
            (const uint4*)(g_wthi + (size_t)ws * HH * HH),
            (const uint4*)(g_wtlo + (size_t)ws * HH * HH)};
#pragma unroll
        for (int ti = 0; ti < 4; ti++) {
            const uint4* src = srcs[ti];
            char* dst = sm + ti * TILE_B;
#pragma unroll
            for (int t = 0; t < 4; t++) {
                int c = tid + t * 512;
                int r = c >> 4, q = c & 15;
                *(uint4*)(dst + r * (LDT * 2) + q * 16) = src[r * 16 + q];
            }
        }
    }
    __syncthreads();

    int lane = tid & 31, wid = tid >> 5;
    o.warpM = wid & 3;
    o.warpN = wid >> 2;
    o.g = lane >> 2;
    o.tg = lane & 3;

    uint32_t smbase = smem_u32(sm);
    uint32_t aOff = (uint32_t)((o.warpM * 32 + (lane & 15)) * LDT + ((lane & 16) ? 8 : 0)) * 2;
    uint32_t bOff = (uint32_t)((o.warpN * 32 + (lane & 7) + ((lane & 16) ? 8 : 0)) * LDT +
                               ((lane & 8) ? 8 : 0)) * 2;

    uint32_t aH = smbase + aOff;
    uint32_t aL = smbase + TILE_B + aOff;
    uint32_t bH = smbase + 2 * TILE_B + bOff;
    uint32_t bL = smbase + 3 * TILE_B + bOff;

#pragma unroll
    for (int mi = 0; mi < 2; mi++)
#pragma unroll
        for (int nf = 0; nf < 4; nf++)
#pragma unroll
            for (int j = 0; j < 4; j++) o.acc[mi][nf][j] = 0.f;

#pragma unroll
    for (int kc = 0; kc < 8; kc++) {
        uint32_t kb = kc * 32;
        uint32_t ah[2][4], al[2][4];
        LDMX4(ah[0][0], ah[0][1], ah[0][2], ah[0][3], aH + kb);
        LDMX4(ah[1][0], ah[1][1], ah[1][2], ah[1][3], aH + 16 * LDT * 2 + kb);
        LDMX4(al[0][0], al[0][1], al[0][2], al[0][3], aL + kb);
        LDMX4(al[1][0], al[1][1], al[1][2], al[1][3], aL + 16 * LDT * 2 + kb);
#pragma unroll
        for (int p = 0; p < 2; p++) {
            uint32_t bh0, bh1, bh2, bh3, bl0, bl1, bl2, bl3;
            LDMX4(bh0, bh1, bh2, bh3, bH + p * (16 * LDT * 2) + kb);
            LDMX4(bl0, bl1, bl2, bl3, bL + p * (16 * LDT * 2) + kb);
#pragma unroll
            for (int mi = 0; mi < 2; mi++) {
                MMA16816(o.acc[mi][2 * p],     ah[mi][0], ah[mi][1], ah[mi][2], ah[mi][3], bh0, bh1);
                MMA16816(o.acc[mi][2 * p + 1], ah[mi][0], ah[mi][1], ah[mi][2], ah[mi][3], bh2, bh3);
                MMA16816(o.acc[mi][2 * p],     ah[mi][0], ah[mi][1], ah[mi][2], ah[mi][3], bl0, bl1);
                MMA16816(o.acc[mi][2 * p + 1], ah[mi][0], ah[mi][1], ah[mi][2], ah[mi][3], bl2, bl3);
                MMA16816(o.acc[mi][2 * p],     al[mi][0], al[mi][1], al[mi][2], al[mi][3], bh0, bh1);
                MMA16816(o.acc[mi][2 * p + 1], al[mi][0], al[mi][1], al[mi][2], al[mi][3], bh2, bh3);
            }
        }
    }
}

// ---------------- RGCN GEMM (uses shared body) ----------------
__global__ void __launch_bounds__(512) k_rgcn_mma(const float* __restrict__ bias, int li) {
    extern __shared__ char sm[];
    __shared__ float s_bias[HH];
    int tid = threadIdx.x;
    int cb = blockIdx.x, mb = blockIdx.y;
    int m0 = mb * 128;
    if (cb == 8 && tid < HH) s_bias[tid] = bias[li * HH + tid];

    TileOut o;
    hmma_tile(sm, g_xhi, g_xlo, m0, li * 9 + cb, o);

#pragma unroll
    for (int mi = 0; mi < 2; mi++) {
        int r0 = m0 + o.warpM * 32 + mi * 16 + o.g;
#pragma unroll
        for (int nf = 0; nf < 4; nf++) {
            int col = o.warpN * 32 + nf * 8 + o.tg * 2;
            if (cb < 8) {
                float2* z0 = (float2*)(g_z + (size_t)r0 * (RR * HH) + cb * HH + col);
                float2* z1 = (float2*)(g_z + (size_t)(r0 + 8) * (RR * HH) + cb * HH + col);
                *z0 = make_float2(o.acc[mi][nf][0], o.acc[mi][nf][1]);
                *z1 = make_float2(o.acc[mi][nf][2], o.acc[mi][nf][3]);
            } else {
                float b0 = s_bias[col], b1 = s_bias[col + 1];
                float2* y0 = (float2*)(g_y + (size_t)r0 * HH + col);
                float2* y1 = (float2*)(g_y + (size_t)(r0 + 8) * HH + col);
                *y0 = make_float2(o.acc[mi][nf][0] + b0, o.acc[mi][nf][1] + b1);
                *y1 = make_float2(o.acc[mi][nf][2] + b0, o.acc[mi][nf][3] + b1);
            }
        }
    }
}

// ---------------- tail GEMMs via HMMA ----------------
// mode 0 (pre): bx<72 -> xw (ws 29..31), else C (ws 27). mode 1 (post): A (ws 28)
__global__ void __launch_bounds__(512) k_bgemm(int mode, const float* __restrict__ gbih,
                                               const float* __restrict__ linNb) {
    extern __shared__ char sm[];
    int bx = blockIdx.x;
    const __nv_bfloat16 *Ahi, *Alo;
    const float* bias;
    float* out;
    int ws, m0, ostride;
    if (mode == 0) {
        if (bx < 72) {
            int s = bx % 3;
            ws = 29 + s; m0 = (bx / 3) * 128;
            Ahi = g_sihi; Alo = g_silo;
            bias = gbih + s * 128;
            out = g_xw + s * 128; ostride = 3 * HH;
        } else {
            ws = 27; m0 = (bx - 72) * 128;
            Ahi = g_xhi; Alo = g_xlo;
            bias = linNb;
            out = g_C; ostride = HH;
        }
    } else {
        ws = 28; m0 = bx * 128;
        Ahi = g_sohi; Alo = g_solo;
        bias = nullptr;
        out = g_A; ostride = HH;
    }

    TileOut o;
    hmma_tile(sm, Ahi, Alo, m0, ws, o);

#pragma unroll
    for (int mi = 0; mi < 2; mi++) {
        int r0 = m0 + o.warpM * 32 + mi * 16 + o.g;
#pragma unroll
        for (int nf = 0; nf < 4; nf++) {
            int col = o.warpN * 32 + nf * 8 + o.tg * 2;
            float b0 = bias ? bias[col] : 0.f;
            float b1 = bias ? bias[col + 1] : 0.f;
            float2* o0 = (float2*)(out + (size_t)r0 * ostride + col);
            float2* o1 = (float2*)(out + (size_t)(r0 + 8) * ostride + col);
            *o0 = make_float2(o.acc[mi][nf][0] + b0, o.acc[mi][nf][1] + b1);
            *o1 = make_float2(o.acc[mi][nf][2] + b0, o.acc[mi][nf][3] + b1);
        }
    }
}

// ------------- gather + relu + bf16 split (R7) + optional counter re-zero --
__device__ __forceinline__ int segoff(int s) { return g_off[s] + g_bt2[s >> 10]; }

__global__ void __launch_bounds__(256) k_gather_relu(int zero_cnt) {
    int gtid = blockIdx.x * blockDim.x + threadIdx.x;
    if (zero_cnt && gtid < NSEG) { g_cnt[gtid] = 0; g_cur[gtid] = 0; }
    int node = gtid >> 5;
    int lane = threadIdx.x & 31;
    if (node >= NN) return;

    float4 acc = ((const float4*)(g_y + (size_t)node * HH))[lane];
    int st = segoff(node * RR);
#pragma unroll
    for (int r = 0; r < RR; r++) {
        int sn = node * RR + r + 1;
        int en = (sn < NSEG) ? segoff(sn) : EE;
        int cnt = en - st;
        if (cnt > 0) {
            float4 a = make_float4(0.f, 0.f, 0.f, 0.f);
            for (int j = st; j < en; j++) {
                int src = g_esrc[j];
                float4 z = *(const float4*)&g_z[(size_t)src * (RR * HH) + r * HH + lane * 4];
                a.x += z.x; a.y += z.y; a.z += z.z; a.w += z.w;
            }
            float sc = 1.0f / (float)cnt;
            acc.x += a.x * sc; acc.y += a.y * sc;
            acc.z += a.z * sc; acc.w += a.w * sc;
        }
        st = en;
    }
    acc.x = fmaxf(acc.x, 0.f); acc.y = fmaxf(acc.y, 0.f);
    acc.z = fmaxf(acc.z, 0.f); acc.w = fmaxf(acc.w, 0.f);

    ((float4*)(g_x + (size_t)node * HH))[lane] = acc;

    __nv_bfloat162 h0 = make_bfloat162(__float2bfloat16(acc.x), __float2bfloat16(acc.y));
    __nv_bfloat162 h1 = make_bfloat162(__float2bfloat16(acc.z), __float2bfloat16(acc.w));
    __nv_bfloat162 l0 = make_bfloat162(
        __float2bfloat16(acc.x - __bfloat162float(h0.x)),
        __float2bfloat16(acc.y - __bfloat162float(h0.y)));
    __nv_bfloat162 l1 = make_bfloat162(
        __float2bfloat16(acc.z - __bfloat162float(h1.x)),
        __float2bfloat16(acc.w - __bfloat162float(h1.y)));
    ((__nv_bfloat162*)(g_xhi + (size_t)node * HH))[lane * 2] = h0;
    ((__nv_bfloat162*)(g_xhi + (size_t)node * HH))[lane * 2 + 1] = h1;
    ((__nv_bfloat162*)(g_xlo + (size_t)node * HH))[lane * 2] = l0;
    ((__nv_bfloat162*)(g_xlo + (size_t)node * HH))[lane * 2 + 1] = l1;
}

// ---------------- pool + action head + sos (fused, block per graph) --------
__global__ void k_pool_action_sos(const int* __restrict__ nodes_bs,
                                  const float* __restrict__ wA, const float* __restrict__ bA,
                                  const float* __restrict__ wAf, const float* __restrict__ bAf,
                                  const int* __restrict__ act, const float* __restrict__ embA,
                                  float* __restrict__ out) {
    int b = blockIdx.x, o = threadIdx.x;
    __shared__ float sg[HH], t1[HH];
    float s = 0.f;
    const float* xp = g_x + (size_t)b * NPG * HH + o;
#pragma unroll 4
    for (int j = 0; j < NPG; j++) s += xp[j * HH];
    s /= (float)nodes_bs[b];
    g_hG[b * HH + o] = s;
    sg[o] = s;
    float sv = embA[act[b] * HH + o];
    size_t sidx = (size_t)b * LL * HH + o;
    g_seqin[sidx] = sv;
    __nv_bfloat16 hi = __float2bfloat16(sv);
    g_sihi[sidx] = hi;
    g_silo[sidx] = __float2bfloat16(sv - __bfloat162float(hi));
    __syncthreads();
    float acc = bA[o];
    const float* w = wA + o * HH;
#pragma unroll 8
    for (int h = 0; h < HH; h += 4) {
        float4 w4 = *(const float4*)&w[h];
        acc += sg[h] * w4.x + sg[h + 1] * w4.y + sg[h + 2] * w4.z + sg[h + 3] * w4.w;
    }
    t1[o] = fmaxf(acc, 0.f);
    __syncthreads();
    if (o < VAC) {
        float a2 = bAf[o];
        const float* w2 = wAf + o * HH;
#pragma unroll 8
        for (int h = 0; h < HH; h += 4) {
            float4 w4 = *(const float4*)&w2[h];
            a2 += t1[h] * w4.x + t1[h + 1] * w4.y + t1[h + 2] * w4.z + t1[h + 3] * w4.w;
        }
        out[b * VAC + o] = a2;
    }
}

// ---------------- GRU input assembly (+ split) ----------------
__global__ void k_seqemb(const float* __restrict__ seq) {
    int t = blockIdx.x;
    int b = blockIdx.y;
    int h = threadIdx.x;
    __shared__ float s[NPG];
    s[h] = seq[(size_t)(b * NPG + h) * LL + t];
    __syncthreads();
    float acc = 0.f;
    for (int j = 0; j < NPG; j++) {
        float sv = s[j];
        if (sv != 0.0f)
            acc += sv * g_x[(size_t)(b * NPG + j) * HH + h];
    }
    size_t idx = ((size_t)b * LL + t + 1) * HH + h;
    g_seqin[idx] = acc;
    __nv_bfloat16 hi = __float2bfloat16(acc);
    g_sihi[idx] = hi;
    g_silo[idx] = __float2bfloat16(acc - __bfloat162float(hi));
}

// ---------------- GRU scan: register-resident weights (+ split out) --------
__global__ void __launch_bounds__(384, 1) k_gru(const float* __restrict__ w_hh,
                                                const float* __restrict__ b_hh,
                                                const int* __restrict__ len_seq) {
    int b = blockIdx.x;
    int g = threadIdx.x;
    __shared__ __align__(16) float sh[HH];
    __shared__ float sg[3 * HH];

    float4 w[32];
    const float4* wp = (const float4*)(w_hh + (size_t)g * HH);
#pragma unroll
    for (int k = 0; k < 32; k++) w[k] = wp[k];
    float bg = b_hh[g];
    if (g < HH) sh[g] = g_hG[b * HH + g];
    int ls = len_seq[b];
    __syncthreads();

    const float4* sh4 = (const float4*)sh;
    for (int t = 0; t < LL; t++) {
        float a0 = 0.f, a1 = 0.f, a2 = 0.f, a3 = 0.f;
#pragma unroll
        for (int k = 0; k < 32; k += 4) {
            float4 h0 = sh4[k], h1 = sh4[k + 1], h2 = sh4[k + 2], h3 = sh4[k + 3];
            a0 += h0.x * w[k].x + h0.y * w[k].y + h0.z * w[k].z + h0.w * w[k].w;
            a1 += h1.x * w[k + 1].x + h1.y * w[k + 1].y + h1.z * w[k + 1].z + h1.w * w[k + 1].w;
            a2 += h2.x * w[k + 2].x + h2.y * w[k + 2].y + h2.z * w[k + 2].z + h2.w * w[k + 2].w;
            a3 += h3.x * w[k + 3].x + h3.y * w[k + 3].y + h3.z * w[k + 3].z + h3.w * w[k + 3].w;
        }
        sg[g] = bg + (a0 + a1) + (a2 + a3);
        __syncthreads();
        if (g < HH) {
            const float* xwp = g_xw + ((size_t)b * LL + t) * (3 * HH);
            float rg = 1.f / (1.f + expf(-(xwp[g] + sg[g])));
            float zg = 1.f / (1.f + expf(-(xwp[HH + g] + sg[HH + g])));
            float ng = tanhf(xwp[2 * HH + g] + rg * sg[2 * HH + g]);
            float hnew = (1.f - zg) * ng + zg * sh[g];
            float ov = (t < ls) ? hnew : 0.f;
            size_t oidx = ((size_t)b * LL + t) * HH + g;
            g_seqout[oidx] = ov;
            __nv_bfloat16 hi = __float2bfloat16(ov);
            g_sohi[oidx] = hi;
            g_solo[oidx] = __float2bfloat16(ov - __bfloat162float(hi));
            sh[g] = hnew;
        }
        __syncthreads();
    }
}

// ------- blocked node logits: 4 blocks per graph, A[b] staged in smem ------
__global__ void __launch_bounds__(256) k_logitsB(const float* __restrict__ wf,
                                                 const float* __restrict__ bf,
                                                 float* __restrict__ outN) {
    int b = blockIdx.x >> 2;
    int ng = blockIdx.x & 3;
    __shared__ float As[LL * HH];
    int tid = threadIdx.x, w = tid >> 5, lane = tid & 31;
    for (int idx = tid; idx < LL * HH; idx += 256)
        As[idx] = g_A[(size_t)b * LL * HH + idx];
    __syncthreads();
    float4 w4 = *(const float4*)&wf[lane * 4];
    float bias = bf[0];
#pragma unroll
    for (int k = 0; k < 4; k++) {
        int node = ng * 32 + w + 8 * k;
        int i = b * NPG + node;
        float4 c4 = *(const float4*)&g_C[(size_t)i * HH + lane * 4];
        for (int t0 = 0; t0 < LL; t0 += 4) {
            float s[4];
#pragma unroll
            for (int q = 0; q < 4; q++) {
                float4 a4 = *(const float4*)&As[(t0 + q) * HH + lane * 4];
                s[q] = fmaxf(a4.x + c4.x, 0.f) * w4.x
                     + fmaxf(a4.y + c4.y, 0.f) * w4.y
                     + fmaxf(a4.z + c4.z, 0.f) * w4.z
                     + fmaxf(a4.w + c4.w, 0.f) * w4.w;
            }
#pragma unroll
            for (int off = 16; off; off >>= 1) {
#pragma unroll
                for (int q = 0; q < 4; q++)
                    s[q] += __shfl_down_sync(0xffffffffu, s[q], off);
            }
            if (lane == 0) {
#pragma unroll
                for (int q = 0; q < 4; q++)
                    outN[(size_t)i * LL + t0 + q] = s[q] + bias;
            }
        }
    }
}

// ---------------- per-graph softmax, coalesced (R10) -----------------------
__global__ void __launch_bounds__(256) k_softmax2(float* __restrict__ outN) {
    int b = blockIdx.x;
    __shared__ float sm[LL * 129];
    __shared__ float smax[LL], ssum[LL];
    int tid = threadIdx.x;
    float* base = outN + (size_t)b * NPG * LL;

    for (int idx = tid; idx < NPG * LL; idx += 256) {
        int node = idx / LL, t = idx % LL;
        sm[t * 129 + node] = base[idx];
    }
    __syncthreads();

    int w = tid >> 5, lane = tid & 31;
    for (int t = w; t < LL; t += 8) {
        float v0 = sm[t * 129 + lane];
        float v1 = sm[t * 129 + lane + 32];
        float v2 = sm[t * 129 + lane + 64];
        float v3 = sm[t * 129 + lane + 96];
        float mx = fmaxf(fmaxf(v0, v1), fmaxf(v2, v3));
#pragma unroll
        for (int off = 16; off; off >>= 1)
            mx = fmaxf(mx, __shfl_xor_sync(0xffffffffu, mx, off));
        float e = expf(v0 - mx) + expf(v1 - mx) + expf(v2 - mx) + expf(v3 - mx);
#pragma unroll
        for (int off = 16; off; off >>= 1) e += __shfl_xor_sync(0xffffffffu, e, off);
        if (lane == 0) { smax[t] = mx; ssum[t] = e; }
    }
    __syncthreads();

    for (int idx = tid; idx < NPG * LL; idx += 256) {
        int node = idx / LL, t = idx % LL;
        base[idx] = expf(sm[t * 129 + node] - smax[t]) / ssum[t];
    }
}

// ---------------- launch ----------------
extern "C" void kernel_launch(void* const* d_in, const int* in_sizes, int n_in,
                              void* d_out, int out_size) {
    const int* nodeTypes   = (const int*)d_in[0];
    const int* edge_index  = (const int*)d_in[1];
    const int* edge_attr   = (const int*)d_in[2];
    const int* bs          = (const int*)d_in[3];
    const int* nodes_bs    = (const int*)d_in[4];
    const int* len_seq     = (const int*)d_in[5];
    const float* seq       = (const float*)d_in[6];
    const int* action_in   = (const int*)d_in[7];
    const float* emb_nodes = (const float*)d_in[8];
    const float* emb_act   = (const float*)d_in[9];
    const float* rgcn_rel  = (const float*)d_in[10];
    const float* rgcn_root = (const float*)d_in[11];
    const float* rgcn_bias = (const float*)d_in[12];
    const float* gru_w_ih  = (const float*)d_in[13];
    const float* gru_w_hh  = (const float*)d_in[14];
    const float* gru_b_ih  = (const float*)d_in[15];
    const float* gru_b_hh  = (const float*)d_in[16];
    const float* linA_w    = (const float*)d_in[17];
    const float* linA_b    = (const float*)d_in[18];
    const float* linAf_w   = (const float*)d_in[19];
    const float* linAf_b   = (const float*)d_in[20];
    const float* linN_w    = (const float*)d_in[21];
    const float* linN_b    = (const float*)d_in[22];
    const float* linNf_w   = (const float*)d_in[23];
    const float* linNf_b   = (const float*)d_in[24];

    float* out_action = (float*)d_out;
    float* out_nodes  = out_action + BB * VAC;

    cudaFuncSetAttribute(k_rgcn_mma, cudaFuncAttributeMaxDynamicSharedMemorySize, RGCN_SMEM);
    cudaFuncSetAttribute(k_bgemm, cudaFuncAttributeMaxDynamicSharedMemorySize, RGCN_SMEM);

    // 1: embed+count  2: convw  3: scan1  4: MMA li=0 (profiled slot)
    k_embed_split<<<(NN * HH) / 256, 256>>>(nodeTypes, emb_nodes, edge_index, edge_attr);
    k_convw<<<dim3(16, 32), 256>>>(rgcn_rel, rgcn_root, linN_w, gru_w_ih);
    k_scan1<<<64, 1024>>>();
    k_rgcn_mma<<<dim3(9, 64), 512, RGCN_SMEM>>>(rgcn_bias, 0);

    k_scan2<<<1, 64>>>();
    k_scatter<<<EE / 256, 256>>>(edge_index, edge_attr);

    k_gather_relu<<<NN / 8, 256>>>(1);     // re-zeroes g_cnt/g_cur for next replay
    for (int li = 1; li < 3; li++) {
        k_rgcn_mma<<<dim3(9, 64), 512, RGCN_SMEM>>>(rgcn_bias, li);
        k_gather_relu<<<NN / 8, 256>>>(0);
    }

    k_pool_action_sos<<<BB, HH>>>(nodes_bs, linA_w, linA_b, linAf_w, linAf_b,
                                  action_in, emb_act, out_action);
    k_seqemb<<<dim3(LL - 1, BB), NPG>>>(seq);

    // xw + C via HMMA, then GRU, then A via HMMA
    k_bgemm<<<136, 512, RGCN_SMEM>>>(0, gru_b_ih, linN_b);
    k_gru<<<BB, 3 * HH>>>(gru_w_hh, gru_b_hh, len_seq);
    k_bgemm<<<24, 512, RGCN_SMEM>>>(1, gru_b_ih, linN_b);

    k_logitsB<<<BB * 4, 256>>>(linNf_w, linNf_b, out_nodes);
    k_softmax2<<<BB, 256>>>(out_nodes);
}

// round 15
// speedup vs baseline: 1.2392x; 1.0352x over previous
#include <cuda_runtime.h>
#include <cuda_bf16.h>
#include <math.h>
#include <stdint.h>

#define NN 8192
#define HH 128
#define RR 8
#define BB 64
#define LL 48
#define EE 65536
#define VAC 64
#define NSEG (NN * RR)
#define NPG (NN / BB)

// ---------------- scratch (device globals; no allocation) ----------------
__device__ float g_x[NN * HH];
__device__ __nv_bfloat16 g_xhi[NN * HH];
__device__ __nv_bfloat16 g_xlo[NN * HH];
__device__ __nv_bfloat16 g_wthi[32 * HH * HH];
__device__ __nv_bfloat16 g_wtlo[32 * HH * HH];
__device__ float g_y[NN * HH];
__device__ float g_z[NN * RR * HH];
__device__ int g_cnt[NSEG];                // zero at init; re-zeroed by gather#1
__device__ int g_cur[NSEG];
__device__ int g_off[NSEG];
__device__ int g_bt[64];
__device__ int g_bt2[64];
__device__ int g_esrc[EE];
__device__ float g_hG[BB * HH];
__device__ float g_seqin[BB * LL * HH];
__device__ __nv_bfloat16 g_sihi[BB * LL * HH];
__device__ __nv_bfloat16 g_silo[BB * LL * HH];
__device__ float g_xw[BB * LL * 3 * HH];
__device__ float g_seqout[BB * LL * HH];
__device__ __nv_bfloat16 g_sohi[BB * LL * HH];
__device__ __nv_bfloat16 g_solo[BB * LL * HH];
__device__ float g_A[BB * LL * HH];
__device__ float g_C[NN * HH];

__device__ __forceinline__ uint32_t smem_u32(const void* p) {
    uint32_t a;
    asm("{ .reg .u64 t; cvta.to.shared.u64 t, %1; cvt.u32.u64 %0, t; }" : "=r"(a) : "l"(p));
    return a;
}

// ------- fused prep: embed+split+count (blocks 0..4095) | weight prep ------
// weight blocks: bxx = bx-4096; w = bxx>>4 (0..31), bx_x = bxx&15
// slots 0..26: RGCN transpose+split; 27: linN[:,128:]; 28: linN[:,:128];
// 29..31: gru_w_ih thirds
__global__ void k_prep(const int* __restrict__ nt, const float* __restrict__ emb,
                       const int* __restrict__ ei, const int* __restrict__ ea,
                       const float* __restrict__ rel, const float* __restrict__ root,
                       const float* __restrict__ linN, const float* __restrict__ wih) {
    __shared__ float ts[32][33];
    int bx = blockIdx.x;
    int tid = threadIdx.x;
    if (bx < 4096) {
        int i = bx * 256 + tid;
        if (i < EE) atomicAdd(&g_cnt[ei[EE + i] * RR + ea[i]], 1);
        float v = emb[nt[i >> 7] * HH + (i & 127)];
        g_x[i] = v;
        __nv_bfloat16 hi = __float2bfloat16(v);
        g_xhi[i] = hi;
        g_xlo[i] = __float2bfloat16(v - __bfloat162float(hi));
        return;
    }
    int bxx = bx - 4096;
    int w = bxx >> 4;
    int bx_x = bxx & 15;
    if (w < 27) {
        int li = w / 9, cb = w % 9;
        const float* W = (cb < 8) ? rel + (size_t)(li * 8 + cb) * (HH * HH)
                                  : root + (size_t)li * (HH * HH);
        int tx = (bx_x & 3) * 32;
        int ty = (bx_x >> 2) * 32;
        int r = tid >> 5;
        int c = tid & 31;
#pragma unroll
        for (int i = 0; i < 32; i += 8)
            ts[r + i][c] = W[(size_t)(ty + r + i) * HH + tx + c];
        __syncthreads();
        size_t base = (size_t)w * HH * HH;
#pragma unroll
        for (int i = 0; i < 32; i += 8) {
            float v = ts[c][r + i];
            __nv_bfloat16 hi = __float2bfloat16(v);
            size_t p = base + (size_t)(tx + r + i) * HH + ty + c;
            g_wthi[p] = hi;
            g_wtlo[p] = __float2bfloat16(v - __bfloat162float(hi));
        }
    } else {
        size_t base = (size_t)w * HH * HH;
#pragma unroll
        for (int q = 0; q < 4; q++) {
            int idx = bx_x * 1024 + tid + q * 256;
            int n = idx >> 7, k = idx & 127;
            float v;
            if (w == 27) v = linN[(size_t)n * 256 + 128 + k];
            else if (w == 28) v = linN[(size_t)n * 256 + k];
            else v = wih[(size_t)(w - 29) * 16384 + idx];
            __nv_bfloat16 hi = __float2bfloat16(v);
            g_wthi[base + idx] = hi;
            g_wtlo[base + idx] = __float2bfloat16(v - __bfloat162float(hi));
        }
    }
}

// ---------------- CSR build: block-local scan (scan1) ----------------
__global__ void __launch_bounds__(1024) k_scan1() {
    __shared__ int s[1024];
    int i = blockIdx.x * 1024 + threadIdx.x;
    int v = g_cnt[i];
    s[threadIdx.x] = v;
    __syncthreads();
#pragma unroll
    for (int off = 1; off < 1024; off <<= 1) {
        int t = (threadIdx.x >= off) ? s[threadIdx.x - off] : 0;
        __syncthreads();
        s[threadIdx.x] += t;
        __syncthreads();
    }
    g_off[i] = s[threadIdx.x] - v;
    if (threadIdx.x == 1023) g_bt[blockIdx.x] = s[1023];
}

// ------ scatter with in-block top-level scan (replaces scan2) --------------
__global__ void k_scatter(const int* __restrict__ ei, const int* __restrict__ ea) {
    __shared__ int sbt[64], sbt2[64];
    int tid = threadIdx.x;
    if (tid < 64) sbt[tid] = g_bt[tid];
    __syncthreads();
#pragma unroll
    for (int off = 1; off < 64; off <<= 1) {
        int t = (tid < 64 && tid >= off) ? sbt[tid - off] : 0;
        __syncthreads();
        if (tid < 64) sbt[tid] += t;
        __syncthreads();
    }
    if (tid < 64) sbt2[tid] = (tid == 0) ? 0 : sbt[tid - 1];
    __syncthreads();
    if (blockIdx.x == 0 && tid < 64) g_bt2[tid] = sbt2[tid];
    int e = blockIdx.x * blockDim.x + tid;
    if (e >= EE) return;
    int seg = ei[EE + e] * RR + ea[e];
    int pos = g_off[seg] + sbt2[seg >> 10] + atomicAdd(&g_cur[seg], 1);
    g_esrc[pos] = ei[e];
}

// ====== shared HMMA tile body: out[128,128] = A[128,128] @ Wslot^T =========
#define LDT 136
#define TILE_B (128 * LDT * 2)
#define RGCN_SMEM (4 * TILE_B)

#define MMA16816(d, a0, a1, a2, a3, b0, b1)                                 \
    asm volatile("mma.sync.aligned.m16n8k16.row.col.f32.bf16.bf16.f32 "     \
                 "{%0,%1,%2,%3}, {%4,%5,%6,%7}, {%8,%9}, {%0,%1,%2,%3};"    \
                 : "+f"((d)[0]), "+f"((d)[1]), "+f"((d)[2]), "+f"((d)[3])   \
                 : "r"(a0), "r"(a1), "r"(a2), "r"(a3), "r"(b0), "r"(b1))

#define LDMX4(r0, r1, r2, r3, addr)                                         \
    asm volatile("ldmatrix.sync.aligned.m8n8.x4.shared.b16 {%0,%1,%2,%3}, [%4];" \
                 : "=r"(r0), "=r"(r1), "=r"(r2), "=r"(r3) : "r"(addr))

struct TileOut {
    float acc[2][4][4];
    int warpM, warpN, g, tg;
};

__device__ __forceinline__ void hmma_tile(char* sm,
                                          const __nv_bfloat16* Ahi, const __nv_bfloat16* Alo,
                                          int m0, int ws, TileOut& o) {
    int tid = threadIdx.x;
    {
        const uint4* srcs[4] = {
            (const uint4*)(Ahi + (size_t)m0 * HH),
            (const uint4*)(Alo + (size_t)m0 * HH),
            (const uint4*)(g_wthi + (size_t)ws * HH * HH),
            (const uint4*)(g_wtlo + (size_t)ws * HH * HH)};
#pragma unroll
        for (int ti = 0; ti < 4; ti++) {
            const uint4* src = srcs[ti];
            char* dst = sm + ti * TILE_B;
#pragma unroll
            for (int t = 0; t < 4; t++) {
                int c = tid + t * 512;
                int r = c >> 4, q = c & 15;
                *(uint4*)(dst + r * (LDT * 2) + q * 16) = src[r * 16 + q];
            }
        }
    }
    __syncthreads();

    int lane = tid & 31, wid = tid >> 5;
    o.warpM = wid & 3;
    o.warpN = wid >> 2;
    o.g = lane >> 2;
    o.tg = lane & 3;

    uint32_t smbase = smem_u32(sm);
    uint32_t aOff = (uint32_t)((o.warpM * 32 + (lane & 15)) * LDT + ((lane & 16) ? 8 : 0)) * 2;
    uint32_t bOff = (uint32_t)((o.warpN * 32 + (lane & 7) + ((lane & 16) ? 8 : 0)) * LDT +
                               ((lane & 8) ? 8 : 0)) * 2;

    uint32_t aH = smbase + aOff;
    uint32_t aL = smbase + TILE_B + aOff;
    uint32_t bH = smbase + 2 * TILE_B + bOff;
    uint32_t bL = smbase + 3 * TILE_B + bOff;

#pragma unroll
    for (int mi = 0; mi < 2; mi++)
#pragma unroll
        for (int nf = 0; nf < 4; nf++)
#pragma unroll
            for (int j = 0; j < 4; j++) o.acc[mi][nf][j] = 0.f;

#pragma unroll
    for (int kc = 0; kc < 8; kc++) {
        uint32_t kb = kc * 32;
        uint32_t ah[2][4], al[2][4];
        LDMX4(ah[0][0], ah[0][1], ah[0][2], ah[0][3], aH + kb);
        LDMX4(ah[1][0], ah[1][1], ah[1][2], ah[1][3], aH + 16 * LDT * 2 + kb);
        LDMX4(al[0][0], al[0][1], al[0][2], al[0][3], aL + kb);
        LDMX4(al[1][0], al[1][1], al[1][2], al[1][3], aL + 16 * LDT * 2 + kb);
#pragma unroll
        for (int p = 0; p < 2; p++) {
            uint32_t bh0, bh1, bh2, bh3, bl0, bl1, bl2, bl3;
            LDMX4(bh0, bh1, bh2, bh3, bH + p * (16 * LDT * 2) + kb);
            LDMX4(bl0, bl1, bl2, bl3, bL + p * (16 * LDT * 2) + kb);
#pragma unroll
            for (int mi = 0; mi < 2; mi++) {
                MMA16816(o.acc[mi][2 * p],     ah[mi][0], ah[mi][1], ah[mi][2], ah[mi][3], bh0, bh1);
                MMA16816(o.acc[mi][2 * p + 1], ah[mi][0], ah[mi][1], ah[mi][2], ah[mi][3], bh2, bh3);
                MMA16816(o.acc[mi][2 * p],     ah[mi][0], ah[mi][1], ah[mi][2], ah[mi][3], bl0, bl1);
                MMA16816(o.acc[mi][2 * p + 1], ah[mi][0], ah[mi][1], ah[mi][2], ah[mi][3], bl2, bl3);
                MMA16816(o.acc[mi][2 * p],     al[mi][0], al[mi][1], al[mi][2], al[mi][3], bh0, bh1);
                MMA16816(o.acc[mi][2 * p + 1], al[mi][0], al[mi][1], al[mi][2], al[mi][3], bh2, bh3);
            }
        }
    }
}

// ---------------- RGCN GEMM (uses shared body) ----------------
__global__ void __launch_bounds__(512) k_rgcn_mma(const float* __restrict__ bias, int li) {
    extern __shared__ char sm[];
    __shared__ float s_bias[HH];
    int tid = threadIdx.x;
    int cb = blockIdx.x, mb = blockIdx.y;
    int m0 = mb * 128;
    if (cb == 8 && tid < HH) s_bias[tid] = bias[li * HH + tid];

    TileOut o;
    hmma_tile(sm, g_xhi, g_xlo, m0, li * 9 + cb, o);

#pragma unroll
    for (int mi = 0; mi < 2; mi++) {
        int r0 = m0 + o.warpM * 32 + mi * 16 + o.g;
#pragma unroll
        for (int nf = 0; nf < 4; nf++) {
            int col = o.warpN * 32 + nf * 8 + o.tg * 2;
            if (cb < 8) {
                float2* z0 = (float2*)(g_z + (size_t)r0 * (RR * HH) + cb * HH + col);
                float2* z1 = (float2*)(g_z + (size_t)(r0 + 8) * (RR * HH) + cb * HH + col);
                *z0 = make_float2(o.acc[mi][nf][0], o.acc[mi][nf][1]);
                *z1 = make_float2(o.acc[mi][nf][2], o.acc[mi][nf][3]);
            } else {
                float b0 = s_bias[col], b1 = s_bias[col + 1];
                float2* y0 = (float2*)(g_y + (size_t)r0 * HH + col);
                float2* y1 = (float2*)(g_y + (size_t)(r0 + 8) * HH + col);
                *y0 = make_float2(o.acc[mi][nf][0] + b0, o.acc[mi][nf][1] + b1);
                *y1 = make_float2(o.acc[mi][nf][2] + b0, o.acc[mi][nf][3] + b1);
            }
        }
    }
}

// ---------------- tail GEMMs via HMMA ----------------
// mode 0 (pre): bx<72 -> xw (ws 29..31), else C (ws 27). mode 1 (post): A (ws 28)
__global__ void __launch_bounds__(512) k_bgemm(int mode, const float* __restrict__ gbih,
                                               const float* __restrict__ linNb) {
    extern __shared__ char sm[];
    int bx = blockIdx.x;
    const __nv_bfloat16 *Ahi, *Alo;
    const float* bias;
    float* out;
    int ws, m0, ostride;
    if (mode == 0) {
        if (bx < 72) {
            int s = bx % 3;
            ws = 29 + s; m0 = (bx / 3) * 128;
            Ahi = g_sihi; Alo = g_silo;
            bias = gbih + s * 128;
            out = g_xw + s * 128; ostride = 3 * HH;
        } else {
            ws = 27; m0 = (bx - 72) * 128;
            Ahi = g_xhi; Alo = g_xlo;
            bias = linNb;
            out = g_C; ostride = HH;
        }
    } else {
        ws = 28; m0 = bx * 128;
        Ahi = g_sohi; Alo = g_solo;
        bias = nullptr;
        out = g_A; ostride = HH;
    }

    TileOut o;
    hmma_tile(sm, Ahi, Alo, m0, ws, o);

#pragma unroll
    for (int mi = 0; mi < 2; mi++) {
        int r0 = m0 + o.warpM * 32 + mi * 16 + o.g;
#pragma unroll
        for (int nf = 0; nf < 4; nf++) {
            int col = o.warpN * 32 + nf * 8 + o.tg * 2;
            float b0 = bias ? bias[col] : 0.f;
            float b1 = bias ? bias[col + 1] : 0.f;
            float2* o0 = (float2*)(out + (size_t)r0 * ostride + col);
            float2* o1 = (float2*)(out + (size_t)(r0 + 8) * ostride + col);
            *o0 = make_float2(o.acc[mi][nf][0] + b0, o.acc[mi][nf][1] + b1);
            *o1 = make_float2(o.acc[mi][nf][2] + b0, o.acc[mi][nf][3] + b1);
        }
    }
}

// ------------- gather + relu + bf16 split (R7) + optional counter re-zero --
__device__ __forceinline__ int segoff(int s) { return g_off[s] + g_bt2[s >> 10]; }

__global__ void __launch_bounds__(256) k_gather_relu(int zero_cnt) {
    int gtid = blockIdx.x * blockDim.x + threadIdx.x;
    if (zero_cnt && gtid < NSEG) { g_cnt[gtid] = 0; g_cur[gtid] = 0; }
    int node = gtid >> 5;
    int lane = threadIdx.x & 31;
    if (node >= NN) return;

    float4 acc = ((const float4*)(g_y + (size_t)node * HH))[lane];
    int st = segoff(node * RR);
#pragma unroll
    for (int r = 0; r < RR; r++) {
        int sn = node * RR + r + 1;
        int en = (sn < NSEG) ? segoff(sn) : EE;
        int cnt = en - st;
        if (cnt > 0) {
            float4 a = make_float4(0.f, 0.f, 0.f, 0.f);
            for (int j = st; j < en; j++) {
                int src = g_esrc[j];
                float4 z = *(const float4*)&g_z[(size_t)src * (RR * HH) + r * HH + lane * 4];
                a.x += z.x; a.y += z.y; a.z += z.z; a.w += z.w;
            }
            float sc = 1.0f / (float)cnt;
            acc.x += a.x * sc; acc.y += a.y * sc;
            acc.z += a.z * sc; acc.w += a.w * sc;
        }
        st = en;
    }
    acc.x = fmaxf(acc.x, 0.f); acc.y = fmaxf(acc.y, 0.f);
    acc.z = fmaxf(acc.z, 0.f); acc.w = fmaxf(acc.w, 0.f);

    ((float4*)(g_x + (size_t)node * HH))[lane] = acc;

    __nv_bfloat162 h0 = make_bfloat162(__float2bfloat16(acc.x), __float2bfloat16(acc.y));
    __nv_bfloat162 h1 = make_bfloat162(__float2bfloat16(acc.z), __float2bfloat16(acc.w));
    __nv_bfloat162 l0 = make_bfloat162(
        __float2bfloat16(acc.x - __bfloat162float(h0.x)),
        __float2bfloat16(acc.y - __bfloat162float(h0.y)));
    __nv_bfloat162 l1 = make_bfloat162(
        __float2bfloat16(acc.z - __bfloat162float(h1.x)),
        __float2bfloat16(acc.w - __bfloat162float(h1.y)));
    ((__nv_bfloat162*)(g_xhi + (size_t)node * HH))[lane * 2] = h0;
    ((__nv_bfloat162*)(g_xhi + (size_t)node * HH))[lane * 2 + 1] = h1;
    ((__nv_bfloat162*)(g_xlo + (size_t)node * HH))[lane * 2] = l0;
    ((__nv_bfloat162*)(g_xlo + (size_t)node * HH))[lane * 2 + 1] = l1;
}

// --------- pool + action + sos | seqemb (fused, grid (LL, BB), 128 thr) ----
__global__ void k_pool_seqemb(const int* __restrict__ nodes_bs,
                              const float* __restrict__ wA, const float* __restrict__ bA,
                              const float* __restrict__ wAf, const float* __restrict__ bAf,
                              const int* __restrict__ act, const float* __restrict__ embA,
                              const float* __restrict__ seq, float* __restrict__ out) {
    int b = blockIdx.y;
    if (blockIdx.x == 0) {
        int o = threadIdx.x;
        __shared__ float sg[HH], t1[HH];
        float s = 0.f;
        const float* xp = g_x + (size_t)b * NPG * HH + o;
#pragma unroll 4
        for (int j = 0; j < NPG; j++) s += xp[j * HH];
        s /= (float)nodes_bs[b];
        g_hG[b * HH + o] = s;
        sg[o] = s;
        float sv = embA[act[b] * HH + o];
        size_t sidx = (size_t)b * LL * HH + o;
        g_seqin[sidx] = sv;
        __nv_bfloat16 hi = __float2bfloat16(sv);
        g_sihi[sidx] = hi;
        g_silo[sidx] = __float2bfloat16(sv - __bfloat162float(hi));
        __syncthreads();
        float acc = bA[o];
        const float* w = wA + o * HH;
#pragma unroll 8
        for (int h = 0; h < HH; h += 4) {
            float4 w4 = *(const float4*)&w[h];
            acc += sg[h] * w4.x + sg[h + 1] * w4.y + sg[h + 2] * w4.z + sg[h + 3] * w4.w;
        }
        t1[o] = fmaxf(acc, 0.f);
        __syncthreads();
        if (o < VAC) {
            float a2 = bAf[o];
            const float* w2 = wAf + o * HH;
#pragma unroll 8
            for (int h = 0; h < HH; h += 4) {
                float4 w4 = *(const float4*)&w2[h];
                a2 += t1[h] * w4.x + t1[h + 1] * w4.y + t1[h + 2] * w4.z + t1[h + 3] * w4.w;
            }
            out[b * VAC + o] = a2;
        }
    } else {
        int t = blockIdx.x - 1;          // 0..LL-2
        int h = threadIdx.x;
        __shared__ float s[NPG];
        s[h] = seq[(size_t)(b * NPG + h) * LL + t];
        __syncthreads();
        float acc = 0.f;
        for (int j = 0; j < NPG; j++) {
            float sv = s[j];
            if (sv != 0.0f)
                acc += sv * g_x[(size_t)(b * NPG + j) * HH + h];
        }
        size_t idx = ((size_t)b * LL + t + 1) * HH + h;
        g_seqin[idx] = acc;
        __nv_bfloat16 hi = __float2bfloat16(acc);
        g_sihi[idx] = hi;
        g_silo[idx] = __float2bfloat16(acc - __bfloat162float(hi));
    }
}

// ---------------- GRU scan: register-resident weights (+ split out) --------
__global__ void __launch_bounds__(384, 1) k_gru(const float* __restrict__ w_hh,
                                                const float* __restrict__ b_hh,
                                                const int* __restrict__ len_seq) {
    int b = blockIdx.x;
    int g = threadIdx.x;
    __shared__ __align__(16) float sh[HH];
    __shared__ float sg[3 * HH];

    float4 w[32];
    const float4* wp = (const float4*)(w_hh + (size_t)g * HH);
#pragma unroll
    for (int k = 0; k < 32; k++) w[k] = wp[k];
    float bg = b_hh[g];
    if (g < HH) sh[g] = g_hG[b * HH + g];
    int ls = len_seq[b];
    __syncthreads();

    const float4* sh4 = (const float4*)sh;
    for (int t = 0; t < LL; t++) {
        float a0 = 0.f, a1 = 0.f, a2 = 0.f, a3 = 0.f;
#pragma unroll
        for (int k = 0; k < 32; k += 4) {
            float4 h0 = sh4[k], h1 = sh4[k + 1], h2 = sh4[k + 2], h3 = sh4[k + 3];
            a0 += h0.x * w[k].x + h0.y * w[k].y + h0.z * w[k].z + h0.w * w[k].w;
            a1 += h1.x * w[k + 1].x + h1.y * w[k + 1].y + h1.z * w[k + 1].z + h1.w * w[k + 1].w;
            a2 += h2.x * w[k + 2].x + h2.y * w[k + 2].y + h2.z * w[k + 2].z + h2.w * w[k + 2].w;
            a3 += h3.x * w[k + 3].x + h3.y * w[k + 3].y + h3.z * w[k + 3].z + h3.w * w[k + 3].w;
        }
        sg[g] = bg + (a0 + a1) + (a2 + a3);
        __syncthreads();
        if (g < HH) {
            const float* xwp = g_xw + ((size_t)b * LL + t) * (3 * HH);
            float rg = 1.f / (1.f + expf(-(xwp[g] + sg[g])));
            float zg = 1.f / (1.f + expf(-(xwp[HH + g] + sg[HH + g])));
            float ng = tanhf(xwp[2 * HH + g] + rg * sg[2 * HH + g]);
            float hnew = (1.f - zg) * ng + zg * sh[g];
            float ov = (t < ls) ? hnew : 0.f;
            size_t oidx = ((size_t)b * LL + t) * HH + g;
            g_seqout[oidx] = ov;
            __nv_bfloat16 hi = __float2bfloat16(ov);
            g_sohi[oidx] = hi;
            g_solo[oidx] = __float2bfloat16(ov - __bfloat162float(hi));
            sh[g] = hnew;
        }
        __syncthreads();
    }
}

// ------- blocked node logits: 4 blocks per graph, A[b] staged in smem ------
__global__ void __launch_bounds__(256) k_logitsB(const float* __restrict__ wf,
                                                 const float* __restrict__ bf,
                                                 float* __restrict__ outN) {
    int b = blockIdx.x >> 2;
    int ng = blockIdx.x & 3;
    __shared__ float As[LL * HH];
    int tid = threadIdx.x, w = tid >> 5, lane = tid & 31;
    for (int idx = tid; idx < LL * HH; idx += 256)
        As[idx] = g_A[(size_t)b * LL * HH + idx];
    __syncthreads();
    float4 w4 = *(const float4*)&wf[lane * 4];
    float bias = bf[0];
#pragma unroll
    for (int k = 0; k < 4; k++) {
        int node = ng * 32 + w + 8 * k;
        int i = b * NPG + node;
        float4 c4 = *(const float4*)&g_C[(size_t)i * HH + lane * 4];
        for (int t0 = 0; t0 < LL; t0 += 4) {
            float s[4];
#pragma unroll
            for (int q = 0; q < 4; q++) {
                float4 a4 = *(const float4*)&As[(t0 + q) * HH + lane * 4];
                s[q] = fmaxf(a4.x + c4.x, 0.f) * w4.x
                     + fmaxf(a4.y + c4.y, 0.f) * w4.y
                     + fmaxf(a4.z + c4.z, 0.f) * w4.z
                     + fmaxf(a4.w + c4.w, 0.f) * w4.w;
            }
#pragma unroll
            for (int off = 16; off; off >>= 1) {
#pragma unroll
                for (int q = 0; q < 4; q++)
                    s[q] += __shfl_down_sync(0xffffffffu, s[q], off);
            }
            if (lane == 0) {
#pragma unroll
                for (int q = 0; q < 4; q++)
                    outN[(size_t)i * LL + t0 + q] = s[q] + bias;
            }
        }
    }
}

// ---------------- per-graph softmax, coalesced (R10) -----------------------
__global__ void __launch_bounds__(256) k_softmax2(float* __restrict__ outN) {
    int b = blockIdx.x;
    __shared__ float sm[LL * 129];
    __shared__ float smax[LL], ssum[LL];
    int tid = threadIdx.x;
    float* base = outN + (size_t)b * NPG * LL;

    for (int idx = tid; idx < NPG * LL; idx += 256) {
        int node = idx / LL, t = idx % LL;
        sm[t * 129 + node] = base[idx];
    }
    __syncthreads();

    int w = tid >> 5, lane = tid & 31;
    for (int t = w; t < LL; t += 8) {
        float v0 = sm[t * 129 + lane];
        float v1 = sm[t * 129 + lane + 32];
        float v2 = sm[t * 129 + lane + 64];
        float v3 = sm[t * 129 + lane + 96];
        float mx = fmaxf(fmaxf(v0, v1), fmaxf(v2, v3));
#pragma unroll
        for (int off = 16; off; off >>= 1)
            mx = fmaxf(mx, __shfl_xor_sync(0xffffffffu, mx, off));
        float e = expf(v0 - mx) + expf(v1 - mx) + expf(v2 - mx) + expf(v3 - mx);
#pragma unroll
        for (int off = 16; off; off >>= 1) e += __shfl_xor_sync(0xffffffffu, e, off);
        if (lane == 0) { smax[t] = mx; ssum[t] = e; }
    }
    __syncthreads();

    for (int idx = tid; idx < NPG * LL; idx += 256) {
        int node = idx / LL, t = idx % LL;
        base[idx] = expf(sm[t * 129 + node] - smax[t]) / ssum[t];
    }
}

// ---------------- launch ----------------
extern "C" void kernel_launch(void* const* d_in, const int* in_sizes, int n_in,
                              void* d_out, int out_size) {
    const int* nodeTypes   = (const int*)d_in[0];
    const int* edge_index  = (const int*)d_in[1];
    const int* edge_attr   = (const int*)d_in[2];
    const int* bs          = (const int*)d_in[3];
    const int* nodes_bs    = (const int*)d_in[4];
    const int* len_seq     = (const int*)d_in[5];
    const float* seq       = (const float*)d_in[6];
    const int* action_in   = (const int*)d_in[7];
    const float* emb_nodes = (const float*)d_in[8];
    const float* emb_act   = (const float*)d_in[9];
    const float* rgcn_rel  = (const float*)d_in[10];
    const float* rgcn_root = (const float*)d_in[11];
    const float* rgcn_bias = (const float*)d_in[12];
    const float* gru_w_ih  = (const float*)d_in[13];
    const float* gru_w_hh  = (const float*)d_in[14];
    const float* gru_b_ih  = (const float*)d_in[15];
    const float* gru_b_hh  = (const float*)d_in[16];
    const float* linA_w    = (const float*)d_in[17];
    const float* linA_b    = (const float*)d_in[18];
    const float* linAf_w   = (const float*)d_in[19];
    const float* linAf_b   = (const float*)d_in[20];
    const float* linN_w    = (const float*)d_in[21];
    const float* linN_b    = (const float*)d_in[22];
    const float* linNf_w   = (const float*)d_in[23];
    const float* linNf_b   = (const float*)d_in[24];

    float* out_action = (float*)d_out;
    float* out_nodes  = out_action + BB * VAC;

    cudaFuncSetAttribute(k_rgcn_mma, cudaFuncAttributeMaxDynamicSharedMemorySize, RGCN_SMEM);
    cudaFuncSetAttribute(k_bgemm, cudaFuncAttributeMaxDynamicSharedMemorySize, RGCN_SMEM);

    // 1: prep  2: scan1  3: scatter  4: MMA li=0 (profiled slot)
    k_prep<<<4096 + 512, 256>>>(nodeTypes, emb_nodes, edge_index, edge_attr,
                                rgcn_rel, rgcn_root, linN_w, gru_w_ih);
    k_scan1<<<64, 1024>>>();
    k_scatter<<<EE / 256, 256>>>(edge_index, edge_attr);
    k_rgcn_mma<<<dim3(9, 64), 512, RGCN_SMEM>>>(rgcn_bias, 0);

    k_gather_relu<<<NN / 8, 256>>>(1);     // re-zeroes g_cnt/g_cur for next replay
    for (int li = 1; li < 3; li++) {
        k_rgcn_mma<<<dim3(9, 64), 512, RGCN_SMEM>>>(rgcn_bias, li);
        k_gather_relu<<<NN / 8, 256>>>(0);
    }

    k_pool_seqemb<<<dim3(LL, BB), HH>>>(nodes_bs, linA_w, linA_b, linAf_w, linAf_b,
                                        action_in, emb_act, seq, out_action);

    k_bgemm<<<136, 512, RGCN_SMEM>>>(0, gru_b_ih, linN_b);
    k_gru<<<BB, 3 * HH>>>(gru_w_hh, gru_b_hh, len_seq);
    k_bgemm<<<24, 512, RGCN_SMEM>>>(1, gru_b_ih, linN_b);

    k_logitsB<<<BB * 4, 256>>>(linNf_w, linNf_b, out_nodes);
    k_softmax2<<<BB, 256>>>(out_nodes);
}